// round 1
// baseline (speedup 1.0000x reference)
#include <cuda_runtime.h>

#define D_MODEL 1024
#define NH 16
#define HD 64
#define BB 2
#define TT 2048
#define MTOT (BB*TT)   // 4096

// Scratch (static device globals: allocation-free at run time)
__device__ float g_Q[BB*NH*TT*HD];
__device__ float g_K[BB*NH*TT*HD];
__device__ float g_V[BB*NH*TT*HD];
__device__ float g_att[MTOT*D_MODEL];

// ---------------------------------------------------------------------------
// SGEMM: C[m,n] = sum_k A[m,k] * W[n,k] + bias[n]
// A: M x K row-major, W: N x K row-major (torch (out,in) weight), K=N=1024.
// mode 0/1/2: write to g_Q/g_K/g_V in (b,h,t,d) layout.  mode 3: A := g_att,
// write flat to Cflat.
// BM=BN=128, BK=8, 256 threads, 8x8 per-thread microtile.
// ---------------------------------------------------------------------------
__global__ void __launch_bounds__(256) sgemm_bias(
    const float* __restrict__ A,
    const float* __restrict__ W,
    const float* __restrict__ bias,
    float* __restrict__ Cflat,
    int mode)
{
    const int K = D_MODEL;
    const int N = D_MODEL;
    __shared__ float As[8][128];
    __shared__ float Bs[8][128];

    int tid = threadIdx.x;
    int tx = tid & 15;        // 0..15  (N direction)
    int ty = tid >> 4;        // 0..15  (M direction)
    int lrow = tid >> 1;      // 0..127 loader row
    int lk   = (tid & 1) * 4; // 0 or 4 loader k-offset

    const float* Aeff = (mode == 3) ? g_att : A;
    const float* Ap = Aeff + (size_t)(blockIdx.y * 128 + lrow) * K + lk;
    const float* Bp = W    + (size_t)(blockIdx.x * 128 + lrow) * K + lk;

    float acc[8][8] = {};

    for (int k0 = 0; k0 < K; k0 += 8) {
        float4 a4 = *(const float4*)(Ap + k0);
        float4 b4 = *(const float4*)(Bp + k0);
        __syncthreads();
        As[lk + 0][lrow] = a4.x;
        As[lk + 1][lrow] = a4.y;
        As[lk + 2][lrow] = a4.z;
        As[lk + 3][lrow] = a4.w;
        Bs[lk + 0][lrow] = b4.x;
        Bs[lk + 1][lrow] = b4.y;
        Bs[lk + 2][lrow] = b4.z;
        Bs[lk + 3][lrow] = b4.w;
        __syncthreads();

        #pragma unroll
        for (int kk = 0; kk < 8; kk++) {
            float ar[8], br[8];
            *(float4*)&ar[0] = *(const float4*)&As[kk][ty * 8];
            *(float4*)&ar[4] = *(const float4*)&As[kk][ty * 8 + 4];
            *(float4*)&br[0] = *(const float4*)&Bs[kk][tx * 8];
            *(float4*)&br[4] = *(const float4*)&Bs[kk][tx * 8 + 4];
            #pragma unroll
            for (int i = 0; i < 8; i++)
                #pragma unroll
                for (int j = 0; j < 8; j++)
                    acc[i][j] += ar[i] * br[j];
        }
    }

    // Epilogue
    #pragma unroll
    for (int i = 0; i < 8; i++) {
        int m = blockIdx.y * 128 + ty * 8 + i;
        #pragma unroll
        for (int j = 0; j < 8; j++) {
            int n = blockIdx.x * 128 + tx * 8 + j;
            float v = acc[i][j] + bias[n];
            if (mode == 3) {
                Cflat[(size_t)m * N + n] = v;
            } else {
                int b = m >> 11;       // m / 2048
                int t = m & 2047;
                int h = n >> 6;        // n / 64
                int d = n & 63;
                float* dst = (mode == 0) ? g_Q : (mode == 1) ? g_K : g_V;
                dst[(((size_t)b * NH + h) * TT + t) * HD + d] = v;
            }
        }
    }
}

// ---------------------------------------------------------------------------
// Flash attention, fp32, online softmax.
// Grid: (TT/64, BB*NH). Block: 256 threads.
// Per CTA: 64 query rows of one (b,h); loop over 64-token KV tiles.
// Thread (tx,ty) tx=tid%16, ty=tid/16 owns rows 4*ty+i (i<4),
// score cols tx+16*j (j<4), and output head-dims tx+16*j.
// smem pads: Qs/Ps/Vs ld=68 (16B-aligned rows, distinct banks for the 2
// broadcast groups), Ks ld=65 (conflict-free strided row reads in QK^T).
// ---------------------------------------------------------------------------
#define LDQ 68
#define LDK 65
#define LDV 68
#define LDP 68
#define FLASH_SMEM ((64*LDQ + 64*LDK + 64*LDV + 64*LDP) * 4)

__global__ void __launch_bounds__(256) flash_attn(const int* __restrict__ mask)
{
    extern __shared__ float sm[];
    float* Qs = sm;                       // 64 x LDQ
    float* Ks = Qs + 64 * LDQ;            // 64 x LDK
    float* Vs = Ks + 64 * LDK;            // 64 x LDV
    float* Ps = Vs + 64 * LDV;            // 64 x LDP

    int bh = blockIdx.y;                  // 0..31
    int b  = bh >> 4;
    int h  = bh & 15;
    int q0 = blockIdx.x * 64;

    int tid = threadIdx.x;
    int tx = tid & 15;
    int ty = tid >> 4;

    const float* Qg = g_Q + ((size_t)bh * TT + q0) * HD;
    const float* Kg = g_K + (size_t)bh * TT * HD;
    const float* Vg = g_V + (size_t)bh * TT * HD;
    const int*   Mg = mask + ((size_t)b * TT + q0) * TT;

    // Load Q tile (64x64) into smem (float4, ld=68 keeps 16B alignment)
    #pragma unroll
    for (int i = 0; i < 4; i++) {
        int idx = tid + i * 256;          // float4 index 0..1023
        int r = idx >> 4;
        int c = (idx & 15) * 4;
        *(float4*)&Qs[r * LDQ + c] = *(const float4*)(Qg + idx * 4);
    }

    float o[4][4] = {};
    float mr[4], lr[4];
    #pragma unroll
    for (int i = 0; i < 4; i++) { mr[i] = -1e30f; lr[i] = 0.f; }

    for (int j0 = 0; j0 < TT; j0 += 64) {
        __syncthreads();   // previous tile's PV done before K/V overwrite
        // Load K (scalar stores, ld=65) and V (float4, ld=68)
        #pragma unroll
        for (int i = 0; i < 4; i++) {
            int idx = tid + i * 256;
            int r = idx >> 4;
            int c = (idx & 15) * 4;
            float4 kv = *(const float4*)(Kg + (size_t)j0 * HD + idx * 4);
            Ks[r * LDK + c + 0] = kv.x;
            Ks[r * LDK + c + 1] = kv.y;
            Ks[r * LDK + c + 2] = kv.z;
            Ks[r * LDK + c + 3] = kv.w;
            *(float4*)&Vs[r * LDV + c] = *(const float4*)(Vg + (size_t)j0 * HD + idx * 4);
        }
        __syncthreads();

        // S = Q K^T (64x64 tile), thread fragment s[4][4]
        float s[4][4] = {};
        #pragma unroll 16
        for (int k = 0; k < 64; k++) {
            float qv[4], kv[4];
            #pragma unroll
            for (int i = 0; i < 4; i++) qv[i] = Qs[(4 * ty + i) * LDQ + k];
            #pragma unroll
            for (int j = 0; j < 4; j++) kv[j] = Ks[(tx + 16 * j) * LDK + k];
            #pragma unroll
            for (int i = 0; i < 4; i++)
                #pragma unroll
                for (int j = 0; j < 4; j++)
                    s[i][j] += qv[i] * kv[j];
        }

        // scale + mask
        #pragma unroll
        for (int i = 0; i < 4; i++) {
            const int* mrow = Mg + (size_t)(4 * ty + i) * TT + j0;
            #pragma unroll
            for (int j = 0; j < 4; j++) {
                float v = s[i][j] * 0.125f;   // 1/sqrt(64)
                if (mrow[tx + 16 * j] == 0) v = -1e30f;
                s[i][j] = v;
            }
        }

        // Row max across the 16 lanes sharing each row (lanes grouped by ty)
        float tmax[4];
        #pragma unroll
        for (int i = 0; i < 4; i++) {
            float mx = s[i][0];
            mx = fmaxf(mx, s[i][1]);
            mx = fmaxf(mx, s[i][2]);
            mx = fmaxf(mx, s[i][3]);
            #pragma unroll
            for (int off = 8; off >= 1; off >>= 1)
                mx = fmaxf(mx, __shfl_xor_sync(0xffffffffu, mx, off));
            tmax[i] = mx;
        }

        float alpha[4];
        #pragma unroll
        for (int i = 0; i < 4; i++) {
            float mn = fmaxf(mr[i], tmax[i]);
            alpha[i] = __expf(mr[i] - mn);
            mr[i] = mn;
        }

        // exponentiate, partial row sums
        float tsum[4];
        #pragma unroll
        for (int i = 0; i < 4; i++) {
            float ssum = 0.f;
            #pragma unroll
            for (int j = 0; j < 4; j++) {
                float p = __expf(s[i][j] - mr[i]);
                s[i][j] = p;
                ssum += p;
            }
            #pragma unroll
            for (int off = 8; off >= 1; off >>= 1)
                ssum += __shfl_xor_sync(0xffffffffu, ssum, off);
            tsum[i] = ssum;
        }

        #pragma unroll
        for (int i = 0; i < 4; i++) {
            lr[i] = lr[i] * alpha[i] + tsum[i];
            #pragma unroll
            for (int j = 0; j < 4; j++) o[i][j] *= alpha[i];
        }

        // stage P
        #pragma unroll
        for (int i = 0; i < 4; i++)
            #pragma unroll
            for (int j = 0; j < 4; j++)
                Ps[(4 * ty + i) * LDP + tx + 16 * j] = s[i][j];
        __syncthreads();

        // O += P V
        #pragma unroll 16
        for (int k = 0; k < 64; k++) {
            float pv[4], vv[4];
            #pragma unroll
            for (int i = 0; i < 4; i++) pv[i] = Ps[(4 * ty + i) * LDP + k];
            #pragma unroll
            for (int j = 0; j < 4; j++) vv[j] = Vs[k * LDV + tx + 16 * j];
            #pragma unroll
            for (int i = 0; i < 4; i++)
                #pragma unroll
                for (int j = 0; j < 4; j++)
                    o[i][j] += pv[i] * vv[j];
        }
    }

    // Epilogue: normalize, scatter to (b, t, h*64+d)
    #pragma unroll
    for (int i = 0; i < 4; i++) {
        float inv = 1.0f / lr[i];
        int q = q0 + 4 * ty + i;
        #pragma unroll
        for (int j = 0; j < 4; j++) {
            int d = tx + 16 * j;
            g_att[((size_t)b * TT + q) * D_MODEL + h * HD + d] = o[i][j] * inv;
        }
    }
}

// ---------------------------------------------------------------------------
extern "C" void kernel_launch(void* const* d_in, const int* in_sizes, int n_in,
                              void* d_out, int out_size)
{
    const float* query = (const float*)d_in[0];
    const float* key   = (const float*)d_in[1];
    const float* value = (const float*)d_in[2];
    const int*   mask  = (const int*)d_in[3];
    const float* wq = (const float*)d_in[4];
    const float* bq = (const float*)d_in[5];
    const float* wk = (const float*)d_in[6];
    const float* bk = (const float*)d_in[7];
    const float* wv = (const float*)d_in[8];
    const float* bv = (const float*)d_in[9];
    const float* wo = (const float*)d_in[10];
    const float* bo = (const float*)d_in[11];
    float* out = (float*)d_out;

    dim3 gg(D_MODEL / 128, MTOT / 128);   // (8, 32)

    sgemm_bias<<<gg, 256>>>(query, wq, bq, nullptr, 0);
    sgemm_bias<<<gg, 256>>>(key,   wk, bk, nullptr, 1);
    sgemm_bias<<<gg, 256>>>(value, wv, bv, nullptr, 2);

    cudaFuncSetAttribute(flash_attn,
                         cudaFuncAttributeMaxDynamicSharedMemorySize,
                         FLASH_SMEM);
    flash_attn<<<dim3(TT / 64, BB * NH), 256, FLASH_SMEM>>>(mask);

    sgemm_bias<<<gg, 256>>>(nullptr, wo, bo, out, 3);
}

// round 5
// speedup vs baseline: 1.6322x; 1.6322x over previous
#include <cuda_runtime.h>
#include <cuda_bf16.h>
#include <cstdint>

#define D_MODEL 1024
#define NH 16
#define HD 64
#define BB 2
#define TT 2048
#define MTOT (BB*TT)   // 4096

// Scratch (static device globals: allocation-free at run time)
__device__ float g_Q[BB*NH*TT*HD];
__device__ float g_K[BB*NH*TT*HD];
__device__ float g_V[BB*NH*TT*HD];
__device__ float g_att[MTOT*D_MODEL];

// bf16 split scratch
__device__ __nv_bfloat16 g_ahi[MTOT*D_MODEL];
__device__ __nv_bfloat16 g_alo[MTOT*D_MODEL];
__device__ __nv_bfloat16 g_whi[D_MODEL*D_MODEL];
__device__ __nv_bfloat16 g_wlo[D_MODEL*D_MODEL];

// ===========================================================================
// helpers
// ===========================================================================
__device__ __forceinline__ uint32_t smem_u32(const void* p) {
    uint32_t a;
    asm("{ .reg .u64 t; cvta.to.shared.u64 t, %1; cvt.u32.u64 %0, t; }"
        : "=r"(a) : "l"(p));
    return a;
}

__device__ __forceinline__ void cvt_split(float4 v, uint2& hi, uint2& lo) {
    __nv_bfloat162 h01 = __floats2bfloat162_rn(v.x, v.y);
    __nv_bfloat162 h23 = __floats2bfloat162_rn(v.z, v.w);
    float r0 = v.x - __bfloat162float(__low2bfloat16(h01));
    float r1 = v.y - __bfloat162float(__high2bfloat16(h01));
    float r2 = v.z - __bfloat162float(__low2bfloat16(h23));
    float r3 = v.w - __bfloat162float(__high2bfloat16(h23));
    __nv_bfloat162 l01 = __floats2bfloat162_rn(r0, r1);
    __nv_bfloat162 l23 = __floats2bfloat162_rn(r2, r3);
    hi.x = *(uint32_t*)&h01; hi.y = *(uint32_t*)&h23;
    lo.x = *(uint32_t*)&l01; lo.y = *(uint32_t*)&l23;
}

#define LDMX4(r, addr) \
    asm volatile("ldmatrix.sync.aligned.m8n8.x4.shared.b16 {%0,%1,%2,%3}, [%4];" \
        : "=r"((r)[0]), "=r"((r)[1]), "=r"((r)[2]), "=r"((r)[3]) : "r"(addr))

#define LDMX2(r, addr) \
    asm volatile("ldmatrix.sync.aligned.m8n8.x2.shared.b16 {%0,%1}, [%2];" \
        : "=r"((r)[0]), "=r"((r)[1]) : "r"(addr))

#define MMA16816(c, a, b) \
    asm volatile("mma.sync.aligned.m16n8k16.row.col.f32.bf16.bf16.f32 " \
        "{%0,%1,%2,%3}, {%4,%5,%6,%7}, {%8,%9}, {%0,%1,%2,%3};" \
        : "+f"((c)[0]), "+f"((c)[1]), "+f"((c)[2]), "+f"((c)[3]) \
        : "r"((a)[0]), "r"((a)[1]), "r"((a)[2]), "r"((a)[3]), \
          "r"((b)[0]), "r"((b)[1]))

#define CP_ASYNC16(dst, src) \
    asm volatile("cp.async.cg.shared.global [%0], [%1], 16;" \
        :: "r"(dst), "l"(src))
#define CP_COMMIT() asm volatile("cp.async.commit_group;" ::: "memory")
#define CP_WAIT1()  asm volatile("cp.async.wait_group 1;" ::: "memory")
#define CP_WAIT0()  asm volatile("cp.async.wait_group 0;" ::: "memory")

// ===========================================================================
// Split kernels: fp32 -> (hi, lo) bf16 pairs
// ===========================================================================
__global__ void __launch_bounds__(256) split_act(const float* __restrict__ x, int n4)
{
    int i = blockIdx.x * 256 + threadIdx.x;
    if (i >= n4) return;
    const float4* xp = (const float4*)(x ? x : (const float*)g_att);
    float4 v = xp[i];
    uint2 hi, lo;
    cvt_split(v, hi, lo);
    ((uint2*)g_ahi)[i] = hi;
    ((uint2*)g_alo)[i] = lo;
}

__global__ void __launch_bounds__(256) split_w(const float* __restrict__ w)
{
    int i = blockIdx.x * 256 + threadIdx.x;   // n4 = 1024*1024/4 = 262144
    float4 v = ((const float4*)w)[i];
    uint2 hi, lo;
    cvt_split(v, hi, lo);
    ((uint2*)g_whi)[i] = hi;
    ((uint2*)g_wlo)[i] = lo;
}

// ===========================================================================
// HMMA GEMM with bf16 split: C[m,n] = sum_k A[m,k]*W[n,k] + bias[n]
//   A from g_ahi/g_alo, W from g_whi/g_wlo (both row-major, K contiguous).
// 128x128x32 CTA tile, 8 warps (2M x 4N), warp tile 64x32.
// smem rows padded to 80B -> conflict-free ldmatrix ((5r+c) mod 8 permutes).
// 2-stage cp.async double buffer. mode 0/1/2: scatter g_Q/g_K/g_V; 3: flat.
// ===========================================================================
#define LDSB 80                  // bytes per smem row (32 bf16 + 8 pad)
#define TILE_B (128*LDSB)        // 10240 B per tile
#define STAGE_B (4*TILE_B)       // AHI, ALO, WHI, WLO
#define GEMM_SMEM (2*STAGE_B)    // 81920 B

__global__ void __launch_bounds__(256, 2) tc_gemm(
    const float* __restrict__ bias, float* __restrict__ Cflat, int mode)
{
    extern __shared__ char smc[];
    uint32_t smb = smem_u32(smc);
    int tid = threadIdx.x;
    int lane = tid & 31;
    int wid = tid >> 5;
    int warp_m = wid & 1;        // 2 in M
    int warp_n = wid >> 1;       // 4 in N
    int m0 = blockIdx.y * 128;
    int n0 = blockIdx.x * 128;

    // loader assignment: tid 0-63 -> AHI, 64-127 -> ALO, 128-191 -> WHI, 192-255 -> WLO
    int tile = tid >> 6;
    int ltid = tid & 63;
    const __nv_bfloat16* lsrc =
        (tile == 0) ? g_ahi : (tile == 1) ? g_alo : (tile == 2) ? g_whi : g_wlo;
    int grow0 = (tile < 2) ? m0 : n0;

#define LOAD_STAGE(kc, stg) do {                                              \
    uint32_t sb0 = smb + (stg) * STAGE_B + tile * TILE_B;                     \
    _Pragma("unroll")                                                         \
    for (int j = 0; j < 8; j++) {                                             \
        int rem = ltid + j * 64;                                              \
        int row = rem >> 2, cc = rem & 3;                                     \
        const __nv_bfloat16* gp =                                             \
            lsrc + (size_t)(grow0 + row) * D_MODEL + (kc) * 32 + cc * 8;      \
        uint32_t dst = sb0 + row * LDSB + cc * 16;                            \
        CP_ASYNC16(dst, gp);                                                  \
    }                                                                         \
    CP_COMMIT();                                                              \
} while (0)

    float acc[4][4][4];
    #pragma unroll
    for (int i = 0; i < 4; i++)
        #pragma unroll
        for (int j = 0; j < 4; j++)
            #pragma unroll
            for (int r = 0; r < 4; r++)
                acc[i][j][r] = 0.f;

    // ldmatrix lane address components
    uint32_t arow = warp_m * 64 + (lane & 7) + ((lane >> 3) & 1) * 8;
    uint32_t acol = ((lane >> 4) & 1) * 16;
    uint32_t brow = warp_n * 32 + (lane & 7);
    uint32_t bcol = ((lane >> 3) & 1) * 16;

    LOAD_STAGE(0, 0);

    for (int kc = 0; kc < D_MODEL / 32; kc++) {
        if (kc + 1 < D_MODEL / 32) {
            LOAD_STAGE(kc + 1, (kc + 1) & 1);
            CP_WAIT1();
        } else {
            CP_WAIT0();
        }
        __syncthreads();

        uint32_t sb = smb + (kc & 1) * STAGE_B;
        uint32_t abase = sb + arow * LDSB + acol;
        uint32_t bbase = sb + 2 * TILE_B + brow * LDSB + bcol;

        #pragma unroll
        for (int s = 0; s < 2; s++) {
            uint32_t bh[4][2], bl[4][2];
            #pragma unroll
            for (int jn = 0; jn < 4; jn++) {
                uint32_t ad = bbase + jn * 8 * LDSB + s * 32;
                LDMX2(bh[jn], ad);
                LDMX2(bl[jn], ad + TILE_B);
            }
            #pragma unroll
            for (int im = 0; im < 4; im++) {
                uint32_t ah[4], al[4];
                uint32_t ad = abase + im * 16 * LDSB + s * 32;
                LDMX4(ah, ad);
                LDMX4(al, ad + TILE_B);
                #pragma unroll
                for (int jn = 0; jn < 4; jn++) {
                    MMA16816(acc[im][jn], ah, bh[jn]);
                    MMA16816(acc[im][jn], ah, bl[jn]);
                    MMA16816(acc[im][jn], al, bh[jn]);
                }
            }
        }
        __syncthreads();
    }

    // Epilogue: bias add + store
    #pragma unroll
    for (int im = 0; im < 4; im++) {
        #pragma unroll
        for (int jn = 0; jn < 4; jn++) {
            int m = m0 + warp_m * 64 + im * 16 + (lane >> 2);
            int n = n0 + warp_n * 32 + jn * 8 + (lane & 3) * 2;
            float2 bv = *(const float2*)&bias[n];
            float2 v01 = make_float2(acc[im][jn][0] + bv.x, acc[im][jn][1] + bv.y);
            float2 v23 = make_float2(acc[im][jn][2] + bv.x, acc[im][jn][3] + bv.y);
            if (mode == 3) {
                *(float2*)(Cflat + (size_t)m * D_MODEL + n) = v01;
                *(float2*)(Cflat + (size_t)(m + 8) * D_MODEL + n) = v23;
            } else {
                float* dstb = (mode == 0) ? g_Q : (mode == 1) ? g_K : g_V;
                int h = n >> 6, d = n & 63;
                int b = m >> 11, t = m & 2047;
                size_t base = (((size_t)b * NH + h) * TT) * HD + d;
                *(float2*)(dstb + base + (size_t)t * HD) = v01;
                *(float2*)(dstb + base + (size_t)(t + 8) * HD) = v23;
            }
        }
    }
#undef LOAD_STAGE
}

// ---------------------------------------------------------------------------
// Flash attention, fp32, online softmax (unchanged — round 1 proven).
// ---------------------------------------------------------------------------
#define LDQ 68
#define LDK 65
#define LDV 68
#define LDP 68
#define FLASH_SMEM ((64*LDQ + 64*LDK + 64*LDV + 64*LDP) * 4)

__global__ void __launch_bounds__(256) flash_attn(const int* __restrict__ mask)
{
    extern __shared__ float sm[];
    float* Qs = sm;
    float* Ks = Qs + 64 * LDQ;
    float* Vs = Ks + 64 * LDK;
    float* Ps = Vs + 64 * LDV;

    int bh = blockIdx.y;
    int b  = bh >> 4;
    int h  = bh & 15;
    int q0 = blockIdx.x * 64;

    int tid = threadIdx.x;
    int tx = tid & 15;
    int ty = tid >> 4;

    const float* Qg = g_Q + ((size_t)bh * TT + q0) * HD;
    const float* Kg = g_K + (size_t)bh * TT * HD;
    const float* Vg = g_V + (size_t)bh * TT * HD;
    const int*   Mg = mask + ((size_t)b * TT + q0) * TT;

    #pragma unroll
    for (int i = 0; i < 4; i++) {
        int idx = tid + i * 256;
        int r = idx >> 4;
        int c = (idx & 15) * 4;
        *(float4*)&Qs[r * LDQ + c] = *(const float4*)(Qg + idx * 4);
    }

    float o[4][4] = {};
    float mr[4], lr[4];
    #pragma unroll
    for (int i = 0; i < 4; i++) { mr[i] = -1e30f; lr[i] = 0.f; }

    for (int j0 = 0; j0 < TT; j0 += 64) {
        __syncthreads();
        #pragma unroll
        for (int i = 0; i < 4; i++) {
            int idx = tid + i * 256;
            int r = idx >> 4;
            int c = (idx & 15) * 4;
            float4 kv = *(const float4*)(Kg + (size_t)j0 * HD + idx * 4);
            Ks[r * LDK + c + 0] = kv.x;
            Ks[r * LDK + c + 1] = kv.y;
            Ks[r * LDK + c + 2] = kv.z;
            Ks[r * LDK + c + 3] = kv.w;
            *(float4*)&Vs[r * LDV + c] = *(const float4*)(Vg + (size_t)j0 * HD + idx * 4);
        }
        __syncthreads();

        float s[4][4] = {};
        #pragma unroll 16
        for (int k = 0; k < 64; k++) {
            float qv[4], kv[4];
            #pragma unroll
            for (int i = 0; i < 4; i++) qv[i] = Qs[(4 * ty + i) * LDQ + k];
            #pragma unroll
            for (int j = 0; j < 4; j++) kv[j] = Ks[(tx + 16 * j) * LDK + k];
            #pragma unroll
            for (int i = 0; i < 4; i++)
                #pragma unroll
                for (int j = 0; j < 4; j++)
                    s[i][j] += qv[i] * kv[j];
        }

        #pragma unroll
        for (int i = 0; i < 4; i++) {
            const int* mrow = Mg + (size_t)(4 * ty + i) * TT + j0;
            #pragma unroll
            for (int j = 0; j < 4; j++) {
                float v = s[i][j] * 0.125f;
                if (mrow[tx + 16 * j] == 0) v = -1e30f;
                s[i][j] = v;
            }
        }

        float tmax[4];
        #pragma unroll
        for (int i = 0; i < 4; i++) {
            float mx = s[i][0];
            mx = fmaxf(mx, s[i][1]);
            mx = fmaxf(mx, s[i][2]);
            mx = fmaxf(mx, s[i][3]);
            #pragma unroll
            for (int off = 8; off >= 1; off >>= 1)
                mx = fmaxf(mx, __shfl_xor_sync(0xffffffffu, mx, off));
            tmax[i] = mx;
        }

        float alpha[4];
        #pragma unroll
        for (int i = 0; i < 4; i++) {
            float mn = fmaxf(mr[i], tmax[i]);
            alpha[i] = __expf(mr[i] - mn);
            mr[i] = mn;
        }

        float tsum[4];
        #pragma unroll
        for (int i = 0; i < 4; i++) {
            float ssum = 0.f;
            #pragma unroll
            for (int j = 0; j < 4; j++) {
                float p = __expf(s[i][j] - mr[i]);
                s[i][j] = p;
                ssum += p;
            }
            #pragma unroll
            for (int off = 8; off >= 1; off >>= 1)
                ssum += __shfl_xor_sync(0xffffffffu, ssum, off);
            tsum[i] = ssum;
        }

        #pragma unroll
        for (int i = 0; i < 4; i++) {
            lr[i] = lr[i] * alpha[i] + tsum[i];
            #pragma unroll
            for (int j = 0; j < 4; j++) o[i][j] *= alpha[i];
        }

        #pragma unroll
        for (int i = 0; i < 4; i++)
            #pragma unroll
            for (int j = 0; j < 4; j++)
                Ps[(4 * ty + i) * LDP + tx + 16 * j] = s[i][j];
        __syncthreads();

        #pragma unroll 16
        for (int k = 0; k < 64; k++) {
            float pv[4], vv[4];
            #pragma unroll
            for (int i = 0; i < 4; i++) pv[i] = Ps[(4 * ty + i) * LDP + k];
            #pragma unroll
            for (int j = 0; j < 4; j++) vv[j] = Vs[k * LDV + tx + 16 * j];
            #pragma unroll
            for (int i = 0; i < 4; i++)
                #pragma unroll
                for (int j = 0; j < 4; j++)
                    o[i][j] += pv[i] * vv[j];
        }
    }

    #pragma unroll
    for (int i = 0; i < 4; i++) {
        float inv = 1.0f / lr[i];
        int q = q0 + 4 * ty + i;
        #pragma unroll
        for (int j = 0; j < 4; j++) {
            int d = tx + 16 * j;
            g_att[((size_t)b * TT + q) * D_MODEL + h * HD + d] = o[i][j] * inv;
        }
    }
}

// ---------------------------------------------------------------------------
extern "C" void kernel_launch(void* const* d_in, const int* in_sizes, int n_in,
                              void* d_out, int out_size)
{
    const float* query = (const float*)d_in[0];
    const float* key   = (const float*)d_in[1];
    const float* value = (const float*)d_in[2];
    const int*   mask  = (const int*)d_in[3];
    const float* wq = (const float*)d_in[4];
    const float* bq = (const float*)d_in[5];
    const float* wk = (const float*)d_in[6];
    const float* bk = (const float*)d_in[7];
    const float* wv = (const float*)d_in[8];
    const float* bv = (const float*)d_in[9];
    const float* wo = (const float*)d_in[10];
    const float* bo = (const float*)d_in[11];
    float* out = (float*)d_out;

    cudaFuncSetAttribute(tc_gemm,
                         cudaFuncAttributeMaxDynamicSharedMemorySize,
                         GEMM_SMEM);
    cudaFuncSetAttribute(flash_attn,
                         cudaFuncAttributeMaxDynamicSharedMemorySize,
                         FLASH_SMEM);

    dim3 gg(D_MODEL / 128, MTOT / 128);   // (8, 32)
    const int ACT4 = MTOT * D_MODEL / 4;  // 1048576

    split_act<<<ACT4 / 256, 256>>>(query, ACT4);
    split_w<<<1024, 256>>>(wq);
    tc_gemm<<<gg, 256, GEMM_SMEM>>>(bq, nullptr, 0);

    split_act<<<ACT4 / 256, 256>>>(key, ACT4);
    split_w<<<1024, 256>>>(wk);
    tc_gemm<<<gg, 256, GEMM_SMEM>>>(bk, nullptr, 1);

    split_act<<<ACT4 / 256, 256>>>(value, ACT4);
    split_w<<<1024, 256>>>(wv);
    tc_gemm<<<gg, 256, GEMM_SMEM>>>(bv, nullptr, 2);

    flash_attn<<<dim3(TT / 64, BB * NH), 256, FLASH_SMEM>>>(mask);

    split_act<<<ACT4 / 256, 256>>>(nullptr, ACT4);
    split_w<<<1024, 256>>>(wo);
    tc_gemm<<<gg, 256, GEMM_SMEM>>>(bo, out, 3);
}

// round 6
// speedup vs baseline: 2.8312x; 1.7346x over previous
#include <cuda_runtime.h>
#include <cuda_bf16.h>
#include <cstdint>

#define D_MODEL 1024
#define NH 16
#define HD 64
#define BB 2
#define TT 2048
#define MTOT (BB*TT)   // 4096

// Scratch (static device globals: allocation-free at run time)
__device__ float g_att[MTOT*D_MODEL];

// bf16 hi/lo split scratch
__device__ __nv_bfloat16 g_ahi[MTOT*D_MODEL];
__device__ __nv_bfloat16 g_alo[MTOT*D_MODEL];
__device__ __nv_bfloat16 g_whi[D_MODEL*D_MODEL];
__device__ __nv_bfloat16 g_wlo[D_MODEL*D_MODEL];

// Q/K/V in (b,h,t,d) layout, bf16 hi/lo pairs (written by tc_gemm epilogue)
__device__ __nv_bfloat16 g_Qhi[BB*NH*TT*HD];
__device__ __nv_bfloat16 g_Qlo[BB*NH*TT*HD];
__device__ __nv_bfloat16 g_Khi[BB*NH*TT*HD];
__device__ __nv_bfloat16 g_Klo[BB*NH*TT*HD];
__device__ __nv_bfloat16 g_Vhi[BB*NH*TT*HD];
__device__ __nv_bfloat16 g_Vlo[BB*NH*TT*HD];

// ===========================================================================
// helpers
// ===========================================================================
__device__ __forceinline__ uint32_t smem_u32(const void* p) {
    uint32_t a;
    asm("{ .reg .u64 t; cvta.to.shared.u64 t, %1; cvt.u32.u64 %0, t; }"
        : "=r"(a) : "l"(p));
    return a;
}

__device__ __forceinline__ void cvt_split(float4 v, uint2& hi, uint2& lo) {
    __nv_bfloat162 h01 = __floats2bfloat162_rn(v.x, v.y);
    __nv_bfloat162 h23 = __floats2bfloat162_rn(v.z, v.w);
    float r0 = v.x - __bfloat162float(__low2bfloat16(h01));
    float r1 = v.y - __bfloat162float(__high2bfloat16(h01));
    float r2 = v.z - __bfloat162float(__low2bfloat16(h23));
    float r3 = v.w - __bfloat162float(__high2bfloat16(h23));
    __nv_bfloat162 l01 = __floats2bfloat162_rn(r0, r1);
    __nv_bfloat162 l23 = __floats2bfloat162_rn(r2, r3);
    hi.x = *(uint32_t*)&h01; hi.y = *(uint32_t*)&h23;
    lo.x = *(uint32_t*)&l01; lo.y = *(uint32_t*)&l23;
}

// pair split: (a,b) fp32 -> bf16x2 hi + bf16x2 lo
__device__ __forceinline__ void cvt2(float a, float b, uint32_t& hi, uint32_t& lo) {
    __nv_bfloat162 h = __floats2bfloat162_rn(a, b);
    float ra = a - __bfloat162float(__low2bfloat16(h));
    float rb = b - __bfloat162float(__high2bfloat16(h));
    __nv_bfloat162 l = __floats2bfloat162_rn(ra, rb);
    hi = *(uint32_t*)&h; lo = *(uint32_t*)&l;
}

#define LDMX4(r, addr) \
    asm volatile("ldmatrix.sync.aligned.m8n8.x4.shared.b16 {%0,%1,%2,%3}, [%4];" \
        : "=r"((r)[0]), "=r"((r)[1]), "=r"((r)[2]), "=r"((r)[3]) : "r"(addr))

#define LDMX4T(r, addr) \
    asm volatile("ldmatrix.sync.aligned.m8n8.x4.trans.shared.b16 {%0,%1,%2,%3}, [%4];" \
        : "=r"((r)[0]), "=r"((r)[1]), "=r"((r)[2]), "=r"((r)[3]) : "r"(addr))

#define LDMX2(r, addr) \
    asm volatile("ldmatrix.sync.aligned.m8n8.x2.shared.b16 {%0,%1}, [%2];" \
        : "=r"((r)[0]), "=r"((r)[1]) : "r"(addr))

#define MMA16816(c, a, b) \
    asm volatile("mma.sync.aligned.m16n8k16.row.col.f32.bf16.bf16.f32 " \
        "{%0,%1,%2,%3}, {%4,%5,%6,%7}, {%8,%9}, {%0,%1,%2,%3};" \
        : "+f"((c)[0]), "+f"((c)[1]), "+f"((c)[2]), "+f"((c)[3]) \
        : "r"((a)[0]), "r"((a)[1]), "r"((a)[2]), "r"((a)[3]), \
          "r"((b)[0]), "r"((b)[1]))

#define CP_ASYNC16(dst, src) \
    asm volatile("cp.async.cg.shared.global [%0], [%1], 16;" \
        :: "r"(dst), "l"(src))
#define CP_COMMIT() asm volatile("cp.async.commit_group;" ::: "memory")
#define CP_WAIT1()  asm volatile("cp.async.wait_group 1;" ::: "memory")
#define CP_WAIT0()  asm volatile("cp.async.wait_group 0;" ::: "memory")

// ===========================================================================
// Split kernels: fp32 -> (hi, lo) bf16 pairs
// ===========================================================================
__global__ void __launch_bounds__(256) split_act(const float* __restrict__ x, int n4)
{
    int i = blockIdx.x * 256 + threadIdx.x;
    if (i >= n4) return;
    const float4* xp = (const float4*)(x ? x : (const float*)g_att);
    float4 v = xp[i];
    uint2 hi, lo;
    cvt_split(v, hi, lo);
    ((uint2*)g_ahi)[i] = hi;
    ((uint2*)g_alo)[i] = lo;
}

__global__ void __launch_bounds__(256) split_w(const float* __restrict__ w)
{
    int i = blockIdx.x * 256 + threadIdx.x;
    float4 v = ((const float4*)w)[i];
    uint2 hi, lo;
    cvt_split(v, hi, lo);
    ((uint2*)g_whi)[i] = hi;
    ((uint2*)g_wlo)[i] = lo;
}

// ===========================================================================
// HMMA GEMM with bf16 split (round-5 proven).
// mode 0/1/2: epilogue writes bf16 hi/lo to g_{Q,K,V}{hi,lo} in (b,h,t,d).
// mode 3: fp32 flat output (A := g_att).
// ===========================================================================
#define LDSB 80
#define TILE_B (128*LDSB)
#define STAGE_B (4*TILE_B)
#define GEMM_SMEM (2*STAGE_B)    // 81920 B

__global__ void __launch_bounds__(256, 2) tc_gemm(
    const float* __restrict__ bias, float* __restrict__ Cflat, int mode)
{
    extern __shared__ char smc[];
    uint32_t smb = smem_u32(smc);
    int tid = threadIdx.x;
    int lane = tid & 31;
    int wid = tid >> 5;
    int warp_m = wid & 1;
    int warp_n = wid >> 1;
    int m0 = blockIdx.y * 128;
    int n0 = blockIdx.x * 128;

    int tile = tid >> 6;
    int ltid = tid & 63;
    const __nv_bfloat16* lsrc =
        (tile == 0) ? g_ahi : (tile == 1) ? g_alo : (tile == 2) ? g_whi : g_wlo;
    int grow0 = (tile < 2) ? m0 : n0;

#define LOAD_STAGE(kc, stg) do {                                              \
    uint32_t sb0 = smb + (stg) * STAGE_B + tile * TILE_B;                     \
    _Pragma("unroll")                                                         \
    for (int j = 0; j < 8; j++) {                                             \
        int rem = ltid + j * 64;                                              \
        int row = rem >> 2, cc = rem & 3;                                     \
        const __nv_bfloat16* gp =                                             \
            lsrc + (size_t)(grow0 + row) * D_MODEL + (kc) * 32 + cc * 8;      \
        uint32_t dst = sb0 + row * LDSB + cc * 16;                            \
        CP_ASYNC16(dst, gp);                                                  \
    }                                                                         \
    CP_COMMIT();                                                              \
} while (0)

    float acc[4][4][4];
    #pragma unroll
    for (int i = 0; i < 4; i++)
        #pragma unroll
        for (int j = 0; j < 4; j++)
            #pragma unroll
            for (int r = 0; r < 4; r++)
                acc[i][j][r] = 0.f;

    uint32_t arow = warp_m * 64 + (lane & 7) + ((lane >> 3) & 1) * 8;
    uint32_t acol = ((lane >> 4) & 1) * 16;
    uint32_t brow = warp_n * 32 + (lane & 7);
    uint32_t bcol = ((lane >> 3) & 1) * 16;

    LOAD_STAGE(0, 0);

    for (int kc = 0; kc < D_MODEL / 32; kc++) {
        if (kc + 1 < D_MODEL / 32) {
            LOAD_STAGE(kc + 1, (kc + 1) & 1);
            CP_WAIT1();
        } else {
            CP_WAIT0();
        }
        __syncthreads();

        uint32_t sb = smb + (kc & 1) * STAGE_B;
        uint32_t abase = sb + arow * LDSB + acol;
        uint32_t bbase = sb + 2 * TILE_B + brow * LDSB + bcol;

        #pragma unroll
        for (int s = 0; s < 2; s++) {
            uint32_t bh[4][2], bl[4][2];
            #pragma unroll
            for (int jn = 0; jn < 4; jn++) {
                uint32_t ad = bbase + jn * 8 * LDSB + s * 32;
                LDMX2(bh[jn], ad);
                LDMX2(bl[jn], ad + TILE_B);
            }
            #pragma unroll
            for (int im = 0; im < 4; im++) {
                uint32_t ah[4], al[4];
                uint32_t ad = abase + im * 16 * LDSB + s * 32;
                LDMX4(ah, ad);
                LDMX4(al, ad + TILE_B);
                #pragma unroll
                for (int jn = 0; jn < 4; jn++) {
                    MMA16816(acc[im][jn], ah, bh[jn]);
                    MMA16816(acc[im][jn], ah, bl[jn]);
                    MMA16816(acc[im][jn], al, bh[jn]);
                }
            }
        }
        __syncthreads();
    }

    // Epilogue
    #pragma unroll
    for (int im = 0; im < 4; im++) {
        #pragma unroll
        for (int jn = 0; jn < 4; jn++) {
            int m = m0 + warp_m * 64 + im * 16 + (lane >> 2);
            int n = n0 + warp_n * 32 + jn * 8 + (lane & 3) * 2;
            float2 bv = *(const float2*)&bias[n];
            float2 v01 = make_float2(acc[im][jn][0] + bv.x, acc[im][jn][1] + bv.y);
            float2 v23 = make_float2(acc[im][jn][2] + bv.x, acc[im][jn][3] + bv.y);
            if (mode == 3) {
                *(float2*)(Cflat + (size_t)m * D_MODEL + n) = v01;
                *(float2*)(Cflat + (size_t)(m + 8) * D_MODEL + n) = v23;
            } else {
                __nv_bfloat16* dhi = (mode == 0) ? g_Qhi : (mode == 1) ? g_Khi : g_Vhi;
                __nv_bfloat16* dlo = (mode == 0) ? g_Qlo : (mode == 1) ? g_Klo : g_Vlo;
                int h = n >> 6, d = n & 63;
                int b = m >> 11, t = m & 2047;
                size_t off = (((size_t)b * NH + h) * TT + t) * HD + d;
                uint32_t hi0, lo0, hi1, lo1;
                cvt2(v01.x, v01.y, hi0, lo0);
                cvt2(v23.x, v23.y, hi1, lo1);
                *(uint32_t*)(dhi + off) = hi0;
                *(uint32_t*)(dlo + off) = lo0;
                *(uint32_t*)(dhi + off + 8 * HD) = hi1;
                *(uint32_t*)(dlo + off + 8 * HD) = lo1;
            }
        }
    }
#undef LOAD_STAGE
}

// ===========================================================================
// HMMA flash attention.
// Grid (TT/128, BB*NH), 256 threads. CTA: 128 queries of one (b,h).
// Warp w owns 16 rows; warp S-tile = 16x128, K-dim 64 (QK^T) / 128 (PV).
// 2-term bf16 split on Q,K and P,V (3 MMAs per logical MMA).
// smem rows 144 B (64 bf16 + 8 pad) -> conflict-free ldmatrix phases.
// K/V double-buffered cp.async; Q staged once.
// ===========================================================================
#define FST 18432                 // 128 rows * 144 B
#define F_STAGE (4*FST)           // Khi, Klo, Vhi, Vlo
#define F_QHI (8*FST)
#define F_QLO (9*FST)
#define FLASH_SMEM (10*FST)       // 184320 B

__global__ void __launch_bounds__(256, 1) flash_attn(const int* __restrict__ mask)
{
    extern __shared__ char smc[];
    uint32_t smb = smem_u32(smc);
    int tid = threadIdx.x;
    int lane = tid & 31;
    int wid = tid >> 5;

    int bh = blockIdx.y;
    int b = bh >> 4;
    int h = bh & 15;
    int q0 = blockIdx.x * 128;

    // --- stage Q (hi+lo) once ---
    #pragma unroll
    for (int i = 0; i < 8; i++) {
        int c = tid + i * 256;            // 2048 chunks of 16B
        int tens = c >> 10, c2 = c & 1023;
        int row = c2 >> 3, ch = c2 & 7;
        const __nv_bfloat16* src = (tens ? g_Qlo : g_Qhi)
            + ((size_t)bh * TT + q0 + row) * HD + ch * 8;
        CP_ASYNC16(smb + F_QHI + tens * FST + row * 144 + ch * 16, src);
    }
    CP_COMMIT();

    // --- K/V tile loader ---
    int ltile = tid >> 6;
    int ltid = tid & 63;
    const __nv_bfloat16* lsrc0 =
        ((ltile == 0) ? g_Khi : (ltile == 1) ? g_Klo
                      : (ltile == 2) ? g_Vhi : g_Vlo) + (size_t)bh * TT * HD;

#define LOAD_KV(j0, stg) do {                                                 \
    const __nv_bfloat16* src = lsrc0 + (size_t)(j0) * HD;                     \
    uint32_t dstb = smb + (stg) * F_STAGE + ltile * FST;                      \
    _Pragma("unroll")                                                         \
    for (int i = 0; i < 16; i++) {                                            \
        int c = ltid + i * 64;                                                \
        int row = c >> 3, ch = c & 7;                                         \
        CP_ASYNC16(dstb + row * 144 + ch * 16, src + row * HD + ch * 8);      \
    }                                                                         \
    CP_COMMIT();                                                              \
} while (0)

    LOAD_KV(0, 0);

    // per-thread row indices (2 rows per thread within warp's 16)
    int rowA = q0 + wid * 16 + (lane >> 2);
    const int* m1 = mask + (size_t)b * TT * TT + (size_t)rowA * TT;
    const int* m2 = m1 + 8 * (size_t)TT;

    float o[8][4];
    #pragma unroll
    for (int i = 0; i < 8; i++)
        #pragma unroll
        for (int r = 0; r < 4; r++) o[i][r] = 0.f;
    float mA = -1e30f, mB = -1e30f, lA = 0.f, lB = 0.f;

    uint32_t qbase = smb + F_QHI
        + (wid * 16 + (lane & 7) + ((lane >> 3) & 1) * 8) * 144
        + ((lane >> 4) & 1) * 16;

    for (int jt = 0; jt < TT / 128; jt++) {
        if (jt + 1 < TT / 128) {
            LOAD_KV((jt + 1) * 128, (jt + 1) & 1);
            CP_WAIT1();
        } else {
            CP_WAIT0();
        }
        __syncthreads();

        uint32_t sK = smb + (jt & 1) * F_STAGE;
        uint32_t sV = sK + 2 * FST;

        // ---- S = Q K^T  (16x128 per warp, k=64, 3-term split) ----
        float s[16][4];
        #pragma unroll
        for (int i = 0; i < 16; i++)
            #pragma unroll
            for (int r = 0; r < 4; r++) s[i][r] = 0.f;

        #pragma unroll
        for (int ksp = 0; ksp < 2; ksp++) {
            uint32_t ah0[4], ah1[4], al0[4], al1[4];
            uint32_t qa = qbase + ksp * 64;
            LDMX4(ah0, qa);
            LDMX4(ah1, qa + 32);
            LDMX4(al0, qa + FST);
            LDMX4(al1, qa + FST + 32);
            #pragma unroll
            for (int nf = 0; nf < 16; nf++) {
                uint32_t kb[4], kl[4];
                uint32_t ka = sK + (nf * 8 + (lane & 7)) * 144
                            + ksp * 64 + (lane >> 3) * 16;
                LDMX4(kb, ka);
                LDMX4(kl, ka + FST);
                MMA16816(s[nf], ah0, &kb[0]);
                MMA16816(s[nf], ah0, &kl[0]);
                MMA16816(s[nf], al0, &kb[0]);
                MMA16816(s[nf], ah1, &kb[2]);
                MMA16816(s[nf], ah1, &kl[2]);
                MMA16816(s[nf], al1, &kb[2]);
            }
        }

        // ---- scale + mask ----
        int j0 = jt * 128;
        #pragma unroll
        for (int nf = 0; nf < 16; nf++) {
            int jc = j0 + nf * 8 + 2 * (lane & 3);
            int2 ma = *(const int2*)(m1 + jc);
            int2 mb = *(const int2*)(m2 + jc);
            s[nf][0] = (ma.x == 0) ? -1e30f : s[nf][0] * 0.125f;
            s[nf][1] = (ma.y == 0) ? -1e30f : s[nf][1] * 0.125f;
            s[nf][2] = (mb.x == 0) ? -1e30f : s[nf][2] * 0.125f;
            s[nf][3] = (mb.y == 0) ? -1e30f : s[nf][3] * 0.125f;
        }

        // ---- online softmax (rows rA = lane>>2, rB = rA+8) ----
        float tmA = -1e30f, tmB = -1e30f;
        #pragma unroll
        for (int nf = 0; nf < 16; nf++) {
            tmA = fmaxf(tmA, fmaxf(s[nf][0], s[nf][1]));
            tmB = fmaxf(tmB, fmaxf(s[nf][2], s[nf][3]));
        }
        #pragma unroll
        for (int off = 1; off <= 2; off <<= 1) {
            tmA = fmaxf(tmA, __shfl_xor_sync(0xffffffffu, tmA, off));
            tmB = fmaxf(tmB, __shfl_xor_sync(0xffffffffu, tmB, off));
        }
        float mnA = fmaxf(mA, tmA), mnB = fmaxf(mB, tmB);
        float aA = __expf(mA - mnA), aB = __expf(mB - mnB);
        mA = mnA; mB = mnB;

        float tsA = 0.f, tsB = 0.f;
        #pragma unroll
        for (int nf = 0; nf < 16; nf++) {
            s[nf][0] = __expf(s[nf][0] - mA);
            s[nf][1] = __expf(s[nf][1] - mA);
            s[nf][2] = __expf(s[nf][2] - mB);
            s[nf][3] = __expf(s[nf][3] - mB);
            tsA += s[nf][0] + s[nf][1];
            tsB += s[nf][2] + s[nf][3];
        }
        #pragma unroll
        for (int off = 1; off <= 2; off <<= 1) {
            tsA += __shfl_xor_sync(0xffffffffu, tsA, off);
            tsB += __shfl_xor_sync(0xffffffffu, tsB, off);
        }
        lA = lA * aA + tsA;
        lB = lB * aB + tsB;
        #pragma unroll
        for (int nf = 0; nf < 8; nf++) {
            o[nf][0] *= aA; o[nf][1] *= aA;
            o[nf][2] *= aB; o[nf][3] *= aB;
        }

        // ---- O += P V  (k=128 keys, split on P and V) ----
        #pragma unroll
        for (int ksp = 0; ksp < 4; ksp++) {
            uint32_t pah0[4], pal0[4], pah1[4], pal1[4];
            cvt2(s[4*ksp+0][0], s[4*ksp+0][1], pah0[0], pal0[0]);
            cvt2(s[4*ksp+0][2], s[4*ksp+0][3], pah0[1], pal0[1]);
            cvt2(s[4*ksp+1][0], s[4*ksp+1][1], pah0[2], pal0[2]);
            cvt2(s[4*ksp+1][2], s[4*ksp+1][3], pah0[3], pal0[3]);
            cvt2(s[4*ksp+2][0], s[4*ksp+2][1], pah1[0], pal1[0]);
            cvt2(s[4*ksp+2][2], s[4*ksp+2][3], pah1[1], pal1[1]);
            cvt2(s[4*ksp+3][0], s[4*ksp+3][1], pah1[2], pal1[2]);
            cvt2(s[4*ksp+3][2], s[4*ksp+3][3], pah1[3], pal1[3]);
            #pragma unroll
            for (int nf = 0; nf < 8; nf++) {
                uint32_t vh[4], vl[4];
                uint32_t va = sV + (ksp * 32 + lane) * 144 + nf * 16;
                LDMX4T(vh, va);
                LDMX4T(vl, va + FST);
                MMA16816(o[nf], pah0, &vh[0]);
                MMA16816(o[nf], pah0, &vl[0]);
                MMA16816(o[nf], pal0, &vh[0]);
                MMA16816(o[nf], pah1, &vh[2]);
                MMA16816(o[nf], pah1, &vl[2]);
                MMA16816(o[nf], pal1, &vh[2]);
            }
        }
        __syncthreads();
    }

    // ---- epilogue: normalize, write (b, q, h*64+d) fp32 ----
    float invA = 1.0f / lA, invB = 1.0f / lB;
    float* outp = g_att + ((size_t)b * TT + rowA) * D_MODEL + h * HD + 2 * (lane & 3);
    #pragma unroll
    for (int nf = 0; nf < 8; nf++) {
        *(float2*)(outp + nf * 8) =
            make_float2(o[nf][0] * invA, o[nf][1] * invA);
        *(float2*)(outp + 8 * D_MODEL + nf * 8) =
            make_float2(o[nf][2] * invB, o[nf][3] * invB);
    }
#undef LOAD_KV
}

// ---------------------------------------------------------------------------
extern "C" void kernel_launch(void* const* d_in, const int* in_sizes, int n_in,
                              void* d_out, int out_size)
{
    const float* query = (const float*)d_in[0];
    const float* key   = (const float*)d_in[1];
    const float* value = (const float*)d_in[2];
    const int*   mask  = (const int*)d_in[3];
    const float* wq = (const float*)d_in[4];
    const float* bq = (const float*)d_in[5];
    const float* wk = (const float*)d_in[6];
    const float* bk = (const float*)d_in[7];
    const float* wv = (const float*)d_in[8];
    const float* bv = (const float*)d_in[9];
    const float* wo = (const float*)d_in[10];
    const float* bo = (const float*)d_in[11];
    float* out = (float*)d_out;

    cudaFuncSetAttribute(tc_gemm,
                         cudaFuncAttributeMaxDynamicSharedMemorySize,
                         GEMM_SMEM);
    cudaFuncSetAttribute(flash_attn,
                         cudaFuncAttributeMaxDynamicSharedMemorySize,
                         FLASH_SMEM);

    dim3 gg(D_MODEL / 128, MTOT / 128);   // (8, 32)
    const int ACT4 = MTOT * D_MODEL / 4;

    split_act<<<ACT4 / 256, 256>>>(query, ACT4);
    split_w<<<1024, 256>>>(wq);
    tc_gemm<<<gg, 256, GEMM_SMEM>>>(bq, nullptr, 0);

    split_act<<<ACT4 / 256, 256>>>(key, ACT4);
    split_w<<<1024, 256>>>(wk);
    tc_gemm<<<gg, 256, GEMM_SMEM>>>(bk, nullptr, 1);

    split_act<<<ACT4 / 256, 256>>>(value, ACT4);
    split_w<<<1024, 256>>>(wv);
    tc_gemm<<<gg, 256, GEMM_SMEM>>>(bv, nullptr, 2);

    flash_attn<<<dim3(TT / 128, BB * NH), 256, FLASH_SMEM>>>(mask);

    split_act<<<ACT4 / 256, 256>>>(nullptr, ACT4);
    split_w<<<1024, 256>>>(wo);
    tc_gemm<<<gg, 256, GEMM_SMEM>>>(bo, out, 3);
}

// round 7
// speedup vs baseline: 3.1236x; 1.1033x over previous
#include <cuda_runtime.h>
#include <cuda_bf16.h>
#include <cstdint>

#define D_MODEL 1024
#define NH 16
#define HD 64
#define BB 2
#define TT 2048
#define MTOT (BB*TT)   // 4096

// Scratch (static device globals: allocation-free at run time)
__device__ float g_att[MTOT*D_MODEL];

// bf16 hi/lo split scratch: activations 3 slices (q,k,v / att uses slice 0)
__device__ __nv_bfloat16 g_ahi[3*MTOT*D_MODEL];
__device__ __nv_bfloat16 g_alo[3*MTOT*D_MODEL];
// weights: 4 slices (wq, wk, wv, wo)
__device__ __nv_bfloat16 g_whi[4*D_MODEL*D_MODEL];
__device__ __nv_bfloat16 g_wlo[4*D_MODEL*D_MODEL];

// Q/K/V in (b,h,t,d) layout, bf16 hi/lo pairs
__device__ __nv_bfloat16 g_Qhi[BB*NH*TT*HD];
__device__ __nv_bfloat16 g_Qlo[BB*NH*TT*HD];
__device__ __nv_bfloat16 g_Khi[BB*NH*TT*HD];
__device__ __nv_bfloat16 g_Klo[BB*NH*TT*HD];
__device__ __nv_bfloat16 g_Vhi[BB*NH*TT*HD];
__device__ __nv_bfloat16 g_Vlo[BB*NH*TT*HD];

// mask block flags: [b][qt][kt], 1 = block fully unmasked
__device__ int g_mflag[BB*16*16];

// ===========================================================================
// helpers
// ===========================================================================
__device__ __forceinline__ uint32_t smem_u32(const void* p) {
    uint32_t a;
    asm("{ .reg .u64 t; cvta.to.shared.u64 t, %1; cvt.u32.u64 %0, t; }"
        : "=r"(a) : "l"(p));
    return a;
}

__device__ __forceinline__ void cvt_split(float4 v, uint2& hi, uint2& lo) {
    __nv_bfloat162 h01 = __floats2bfloat162_rn(v.x, v.y);
    __nv_bfloat162 h23 = __floats2bfloat162_rn(v.z, v.w);
    float r0 = v.x - __bfloat162float(__low2bfloat16(h01));
    float r1 = v.y - __bfloat162float(__high2bfloat16(h01));
    float r2 = v.z - __bfloat162float(__low2bfloat16(h23));
    float r3 = v.w - __bfloat162float(__high2bfloat16(h23));
    __nv_bfloat162 l01 = __floats2bfloat162_rn(r0, r1);
    __nv_bfloat162 l23 = __floats2bfloat162_rn(r2, r3);
    hi.x = *(uint32_t*)&h01; hi.y = *(uint32_t*)&h23;
    lo.x = *(uint32_t*)&l01; lo.y = *(uint32_t*)&l23;
}

__device__ __forceinline__ void cvt2(float a, float b, uint32_t& hi, uint32_t& lo) {
    __nv_bfloat162 h = __floats2bfloat162_rn(a, b);
    float ra = a - __bfloat162float(__low2bfloat16(h));
    float rb = b - __bfloat162float(__high2bfloat16(h));
    __nv_bfloat162 l = __floats2bfloat162_rn(ra, rb);
    hi = *(uint32_t*)&h; lo = *(uint32_t*)&l;
}

#define LDMX4(r, addr) \
    asm volatile("ldmatrix.sync.aligned.m8n8.x4.shared.b16 {%0,%1,%2,%3}, [%4];" \
        : "=r"((r)[0]), "=r"((r)[1]), "=r"((r)[2]), "=r"((r)[3]) : "r"(addr))

#define LDMX4T(r, addr) \
    asm volatile("ldmatrix.sync.aligned.m8n8.x4.trans.shared.b16 {%0,%1,%2,%3}, [%4];" \
        : "=r"((r)[0]), "=r"((r)[1]), "=r"((r)[2]), "=r"((r)[3]) : "r"(addr))

#define LDMX2(r, addr) \
    asm volatile("ldmatrix.sync.aligned.m8n8.x2.shared.b16 {%0,%1}, [%2];" \
        : "=r"((r)[0]), "=r"((r)[1]) : "r"(addr))

#define MMA16816(c, a, b) \
    asm volatile("mma.sync.aligned.m16n8k16.row.col.f32.bf16.bf16.f32 " \
        "{%0,%1,%2,%3}, {%4,%5,%6,%7}, {%8,%9}, {%0,%1,%2,%3};" \
        : "+f"((c)[0]), "+f"((c)[1]), "+f"((c)[2]), "+f"((c)[3]) \
        : "r"((a)[0]), "r"((a)[1]), "r"((a)[2]), "r"((a)[3]), \
          "r"((b)[0]), "r"((b)[1]))

#define CP_ASYNC16(dst, src) \
    asm volatile("cp.async.cg.shared.global [%0], [%1], 16;" \
        :: "r"(dst), "l"(src))
#define CP_COMMIT() asm volatile("cp.async.commit_group;" ::: "memory")
#define CP_WAIT1()  asm volatile("cp.async.wait_group 1;" ::: "memory")
#define CP_WAIT0()  asm volatile("cp.async.wait_group 0;" ::: "memory")

// ===========================================================================
// Split kernels (fused): fp32 -> (hi, lo) bf16 pairs
// ===========================================================================
// all 3 activations in one launch: grid (ACT4/256, 3)
__global__ void __launch_bounds__(256) split_a3(
    const float* __restrict__ q, const float* __restrict__ k,
    const float* __restrict__ v)
{
    int z = blockIdx.y;
    int i = blockIdx.x * 256 + threadIdx.x;
    const float* src = (z == 0) ? q : (z == 1) ? k : v;
    float4 val = ((const float4*)src)[i];
    uint2 hi, lo;
    cvt_split(val, hi, lo);
    size_t off = (size_t)z * (MTOT * D_MODEL / 4) + i;
    ((uint2*)g_ahi)[off] = hi;
    ((uint2*)g_alo)[off] = lo;
}

// single activation (g_att) into slice 0
__global__ void __launch_bounds__(256) split_att()
{
    int i = blockIdx.x * 256 + threadIdx.x;
    float4 v = ((const float4*)g_att)[i];
    uint2 hi, lo;
    cvt_split(v, hi, lo);
    ((uint2*)g_ahi)[i] = hi;
    ((uint2*)g_alo)[i] = lo;
}

// all 4 weights in one launch: grid (WH4/256, 4)
__global__ void __launch_bounds__(256) split_w4(
    const float* __restrict__ wq, const float* __restrict__ wk,
    const float* __restrict__ wv, const float* __restrict__ wo)
{
    int z = blockIdx.y;
    int i = blockIdx.x * 256 + threadIdx.x;
    const float* src = (z == 0) ? wq : (z == 1) ? wk : (z == 2) ? wv : wo;
    float4 v = ((const float4*)src)[i];
    uint2 hi, lo;
    cvt_split(v, hi, lo);
    size_t off = (size_t)z * (D_MODEL * D_MODEL / 4) + i;
    ((uint2*)g_whi)[off] = hi;
    ((uint2*)g_wlo)[off] = lo;
}

// ===========================================================================
// Mask block flags: g_mflag[b][qt][kt] = 1 iff mask block 128x128 all nonzero
// grid (16, 16, 2), 256 threads
// ===========================================================================
__global__ void __launch_bounds__(256) mask_flags(const int* __restrict__ mask)
{
    int qt = blockIdx.x, kt = blockIdx.y, b = blockIdx.z;
    int t = threadIdx.x;
    const int* mp = mask + ((size_t)b * TT + qt * 128) * TT + kt * 128;
    int row = t >> 1, ch = (t & 1) * 64;
    bool ok = true;
    #pragma unroll
    for (int i = 0; i < 16; i++) {
        int4 v = *(const int4*)(mp + (size_t)row * TT + ch + i * 4);
        ok = ok && v.x && v.y && v.z && v.w;
    }
    int all = __syncthreads_and((int)ok);
    if (t == 0) g_mflag[(b * 16 + qt) * 16 + kt] = all;
}

// ===========================================================================
// HMMA GEMM with bf16 split (round-5/6 proven inner loop).
// ===========================================================================
#define LDSB 80
#define TILE_B (128*LDSB)
#define STAGE_B (4*TILE_B)
#define GEMM_SMEM (2*STAGE_B)    // 81920 B

// QKV fused: grid (8, 32, 3); z selects activation slice, weight slice, dest
__global__ void __launch_bounds__(256, 2) tc_gemm_qkv(
    const float* __restrict__ bq, const float* __restrict__ bk,
    const float* __restrict__ bv)
{
    extern __shared__ char smc[];
    uint32_t smb = smem_u32(smc);
    int tid = threadIdx.x;
    int lane = tid & 31;
    int wid = tid >> 5;
    int warp_m = wid & 1;
    int warp_n = wid >> 1;
    int m0 = blockIdx.y * 128;
    int n0 = blockIdx.x * 128;
    int z = blockIdx.z;
    const float* bias = (z == 0) ? bq : (z == 1) ? bk : bv;

    int tile = tid >> 6;
    int ltid = tid & 63;
    const __nv_bfloat16* lsrc =
        (tile == 0) ? g_ahi + (size_t)z * MTOT * D_MODEL
      : (tile == 1) ? g_alo + (size_t)z * MTOT * D_MODEL
      : (tile == 2) ? g_whi + (size_t)z * D_MODEL * D_MODEL
                    : g_wlo + (size_t)z * D_MODEL * D_MODEL;
    int grow0 = (tile < 2) ? m0 : n0;

#define LOAD_STAGE(kc, stg) do {                                              \
    uint32_t sb0 = smb + (stg) * STAGE_B + tile * TILE_B;                     \
    _Pragma("unroll")                                                         \
    for (int j = 0; j < 8; j++) {                                             \
        int rem = ltid + j * 64;                                              \
        int row = rem >> 2, cc = rem & 3;                                     \
        const __nv_bfloat16* gp =                                             \
            lsrc + (size_t)(grow0 + row) * D_MODEL + (kc) * 32 + cc * 8;      \
        uint32_t dst = sb0 + row * LDSB + cc * 16;                            \
        CP_ASYNC16(dst, gp);                                                  \
    }                                                                         \
    CP_COMMIT();                                                              \
} while (0)

    float acc[4][4][4];
    #pragma unroll
    for (int i = 0; i < 4; i++)
        #pragma unroll
        for (int j = 0; j < 4; j++)
            #pragma unroll
            for (int r = 0; r < 4; r++)
                acc[i][j][r] = 0.f;

    uint32_t arow = warp_m * 64 + (lane & 7) + ((lane >> 3) & 1) * 8;
    uint32_t acol = ((lane >> 4) & 1) * 16;
    uint32_t brow = warp_n * 32 + (lane & 7);
    uint32_t bcol = ((lane >> 3) & 1) * 16;

    LOAD_STAGE(0, 0);

    for (int kc = 0; kc < D_MODEL / 32; kc++) {
        if (kc + 1 < D_MODEL / 32) {
            LOAD_STAGE(kc + 1, (kc + 1) & 1);
            CP_WAIT1();
        } else {
            CP_WAIT0();
        }
        __syncthreads();

        uint32_t sb = smb + (kc & 1) * STAGE_B;
        uint32_t abase = sb + arow * LDSB + acol;
        uint32_t bbase = sb + 2 * TILE_B + brow * LDSB + bcol;

        #pragma unroll
        for (int s = 0; s < 2; s++) {
            uint32_t bh[4][2], bl[4][2];
            #pragma unroll
            for (int jn = 0; jn < 4; jn++) {
                uint32_t ad = bbase + jn * 8 * LDSB + s * 32;
                LDMX2(bh[jn], ad);
                LDMX2(bl[jn], ad + TILE_B);
            }
            #pragma unroll
            for (int im = 0; im < 4; im++) {
                uint32_t ah[4], al[4];
                uint32_t ad = abase + im * 16 * LDSB + s * 32;
                LDMX4(ah, ad);
                LDMX4(al, ad + TILE_B);
                #pragma unroll
                for (int jn = 0; jn < 4; jn++) {
                    MMA16816(acc[im][jn], ah, bh[jn]);
                    MMA16816(acc[im][jn], ah, bl[jn]);
                    MMA16816(acc[im][jn], al, bh[jn]);
                }
            }
        }
        __syncthreads();
    }

    __nv_bfloat16* dhi = (z == 0) ? g_Qhi : (z == 1) ? g_Khi : g_Vhi;
    __nv_bfloat16* dlo = (z == 0) ? g_Qlo : (z == 1) ? g_Klo : g_Vlo;
    #pragma unroll
    for (int im = 0; im < 4; im++) {
        #pragma unroll
        for (int jn = 0; jn < 4; jn++) {
            int m = m0 + warp_m * 64 + im * 16 + (lane >> 2);
            int n = n0 + warp_n * 32 + jn * 8 + (lane & 3) * 2;
            float2 bv2 = *(const float2*)&bias[n];
            float2 v01 = make_float2(acc[im][jn][0] + bv2.x, acc[im][jn][1] + bv2.y);
            float2 v23 = make_float2(acc[im][jn][2] + bv2.x, acc[im][jn][3] + bv2.y);
            int h = n >> 6, d = n & 63;
            int b = m >> 11, t = m & 2047;
            size_t off = (((size_t)b * NH + h) * TT + t) * HD + d;
            uint32_t hi0, lo0, hi1, lo1;
            cvt2(v01.x, v01.y, hi0, lo0);
            cvt2(v23.x, v23.y, hi1, lo1);
            *(uint32_t*)(dhi + off) = hi0;
            *(uint32_t*)(dlo + off) = lo0;
            *(uint32_t*)(dhi + off + 8 * HD) = hi1;
            *(uint32_t*)(dlo + off + 8 * HD) = lo1;
        }
    }
#undef LOAD_STAGE
}

// Output projection: A = g_ahi/g_alo slice 0, W = weight slice 3, flat fp32 out
__global__ void __launch_bounds__(256, 2) tc_gemm_o(
    const float* __restrict__ bias, float* __restrict__ Cflat)
{
    extern __shared__ char smc[];
    uint32_t smb = smem_u32(smc);
    int tid = threadIdx.x;
    int lane = tid & 31;
    int wid = tid >> 5;
    int warp_m = wid & 1;
    int warp_n = wid >> 1;
    int m0 = blockIdx.y * 128;
    int n0 = blockIdx.x * 128;

    int tile = tid >> 6;
    int ltid = tid & 63;
    const __nv_bfloat16* lsrc =
        (tile == 0) ? g_ahi
      : (tile == 1) ? g_alo
      : (tile == 2) ? g_whi + (size_t)3 * D_MODEL * D_MODEL
                    : g_wlo + (size_t)3 * D_MODEL * D_MODEL;
    int grow0 = (tile < 2) ? m0 : n0;

#define LOAD_STAGE(kc, stg) do {                                              \
    uint32_t sb0 = smb + (stg) * STAGE_B + tile * TILE_B;                     \
    _Pragma("unroll")                                                         \
    for (int j = 0; j < 8; j++) {                                             \
        int rem = ltid + j * 64;                                              \
        int row = rem >> 2, cc = rem & 3;                                     \
        const __nv_bfloat16* gp =                                             \
            lsrc + (size_t)(grow0 + row) * D_MODEL + (kc) * 32 + cc * 8;      \
        uint32_t dst = sb0 + row * LDSB + cc * 16;                            \
        CP_ASYNC16(dst, gp);                                                  \
    }                                                                         \
    CP_COMMIT();                                                              \
} while (0)

    float acc[4][4][4];
    #pragma unroll
    for (int i = 0; i < 4; i++)
        #pragma unroll
        for (int j = 0; j < 4; j++)
            #pragma unroll
            for (int r = 0; r < 4; r++)
                acc[i][j][r] = 0.f;

    uint32_t arow = warp_m * 64 + (lane & 7) + ((lane >> 3) & 1) * 8;
    uint32_t acol = ((lane >> 4) & 1) * 16;
    uint32_t brow = warp_n * 32 + (lane & 7);
    uint32_t bcol = ((lane >> 3) & 1) * 16;

    LOAD_STAGE(0, 0);

    for (int kc = 0; kc < D_MODEL / 32; kc++) {
        if (kc + 1 < D_MODEL / 32) {
            LOAD_STAGE(kc + 1, (kc + 1) & 1);
            CP_WAIT1();
        } else {
            CP_WAIT0();
        }
        __syncthreads();

        uint32_t sb = smb + (kc & 1) * STAGE_B;
        uint32_t abase = sb + arow * LDSB + acol;
        uint32_t bbase = sb + 2 * TILE_B + brow * LDSB + bcol;

        #pragma unroll
        for (int s = 0; s < 2; s++) {
            uint32_t bh[4][2], bl[4][2];
            #pragma unroll
            for (int jn = 0; jn < 4; jn++) {
                uint32_t ad = bbase + jn * 8 * LDSB + s * 32;
                LDMX2(bh[jn], ad);
                LDMX2(bl[jn], ad + TILE_B);
            }
            #pragma unroll
            for (int im = 0; im < 4; im++) {
                uint32_t ah[4], al[4];
                uint32_t ad = abase + im * 16 * LDSB + s * 32;
                LDMX4(ah, ad);
                LDMX4(al, ad + TILE_B);
                #pragma unroll
                for (int jn = 0; jn < 4; jn++) {
                    MMA16816(acc[im][jn], ah, bh[jn]);
                    MMA16816(acc[im][jn], ah, bl[jn]);
                    MMA16816(acc[im][jn], al, bh[jn]);
                }
            }
        }
        __syncthreads();
    }

    #pragma unroll
    for (int im = 0; im < 4; im++) {
        #pragma unroll
        for (int jn = 0; jn < 4; jn++) {
            int m = m0 + warp_m * 64 + im * 16 + (lane >> 2);
            int n = n0 + warp_n * 32 + jn * 8 + (lane & 3) * 2;
            float2 bv2 = *(const float2*)&bias[n];
            *(float2*)(Cflat + (size_t)m * D_MODEL + n) =
                make_float2(acc[im][jn][0] + bv2.x, acc[im][jn][1] + bv2.y);
            *(float2*)(Cflat + (size_t)(m + 8) * D_MODEL + n) =
                make_float2(acc[im][jn][2] + bv2.x, acc[im][jn][3] + bv2.y);
        }
    }
#undef LOAD_STAGE
}

// ===========================================================================
// HMMA flash attention (round-6 proven) + mask block-flag fast path.
// ===========================================================================
#define FST 18432                 // 128 rows * 144 B
#define F_STAGE (4*FST)
#define F_QHI (8*FST)
#define F_QLO (9*FST)
#define FLASH_SMEM (10*FST)       // 184320 B

__global__ void __launch_bounds__(256, 1) flash_attn(const int* __restrict__ mask)
{
    extern __shared__ char smc[];
    uint32_t smb = smem_u32(smc);
    int tid = threadIdx.x;
    int lane = tid & 31;
    int wid = tid >> 5;

    int bh = blockIdx.y;
    int b = bh >> 4;
    int h = bh & 15;
    int q0 = blockIdx.x * 128;

    // stage Q (hi+lo) once
    #pragma unroll
    for (int i = 0; i < 8; i++) {
        int c = tid + i * 256;
        int tens = c >> 10, c2 = c & 1023;
        int row = c2 >> 3, ch = c2 & 7;
        const __nv_bfloat16* src = (tens ? g_Qlo : g_Qhi)
            + ((size_t)bh * TT + q0 + row) * HD + ch * 8;
        CP_ASYNC16(smb + F_QHI + tens * FST + row * 144 + ch * 16, src);
    }
    CP_COMMIT();

    int ltile = tid >> 6;
    int ltid = tid & 63;
    const __nv_bfloat16* lsrc0 =
        ((ltile == 0) ? g_Khi : (ltile == 1) ? g_Klo
                      : (ltile == 2) ? g_Vhi : g_Vlo) + (size_t)bh * TT * HD;

#define LOAD_KV(j0, stg) do {                                                 \
    const __nv_bfloat16* src = lsrc0 + (size_t)(j0) * HD;                     \
    uint32_t dstb = smb + (stg) * F_STAGE + ltile * FST;                      \
    _Pragma("unroll")                                                         \
    for (int i = 0; i < 16; i++) {                                            \
        int c = ltid + i * 64;                                                \
        int row = c >> 3, ch = c & 7;                                         \
        CP_ASYNC16(dstb + row * 144 + ch * 16, src + row * HD + ch * 8);      \
    }                                                                         \
    CP_COMMIT();                                                              \
} while (0)

    LOAD_KV(0, 0);

    int rowA = q0 + wid * 16 + (lane >> 2);
    const int* m1 = mask + (size_t)b * TT * TT + (size_t)rowA * TT;
    const int* m2 = m1 + 8 * (size_t)TT;
    const int* fl = g_mflag + (b * 16 + blockIdx.x) * 16;

    float o[8][4];
    #pragma unroll
    for (int i = 0; i < 8; i++)
        #pragma unroll
        for (int r = 0; r < 4; r++) o[i][r] = 0.f;
    float mA = -1e30f, mB = -1e30f, lA = 0.f, lB = 0.f;

    uint32_t qbase = smb + F_QHI
        + (wid * 16 + (lane & 7) + ((lane >> 3) & 1) * 8) * 144
        + ((lane >> 4) & 1) * 16;

    for (int jt = 0; jt < TT / 128; jt++) {
        if (jt + 1 < TT / 128) {
            LOAD_KV((jt + 1) * 128, (jt + 1) & 1);
            CP_WAIT1();
        } else {
            CP_WAIT0();
        }
        __syncthreads();

        uint32_t sK = smb + (jt & 1) * F_STAGE;
        uint32_t sV = sK + 2 * FST;

        // ---- S = Q K^T ----
        float s[16][4];
        #pragma unroll
        for (int i = 0; i < 16; i++)
            #pragma unroll
            for (int r = 0; r < 4; r++) s[i][r] = 0.f;

        #pragma unroll
        for (int ksp = 0; ksp < 2; ksp++) {
            uint32_t ah0[4], ah1[4], al0[4], al1[4];
            uint32_t qa = qbase + ksp * 64;
            LDMX4(ah0, qa);
            LDMX4(ah1, qa + 32);
            LDMX4(al0, qa + FST);
            LDMX4(al1, qa + FST + 32);
            #pragma unroll
            for (int nf = 0; nf < 16; nf++) {
                uint32_t kb[4], kl[4];
                uint32_t ka = sK + (nf * 8 + (lane & 7)) * 144
                            + ksp * 64 + (lane >> 3) * 16;
                LDMX4(kb, ka);
                LDMX4(kl, ka + FST);
                MMA16816(s[nf], ah0, &kb[0]);
                MMA16816(s[nf], ah0, &kl[0]);
                MMA16816(s[nf], al0, &kb[0]);
                MMA16816(s[nf], ah1, &kb[2]);
                MMA16816(s[nf], ah1, &kl[2]);
                MMA16816(s[nf], al1, &kb[2]);
            }
        }

        // ---- scale + mask (block-flag fast path) ----
        if (fl[jt]) {
            #pragma unroll
            for (int nf = 0; nf < 16; nf++) {
                s[nf][0] *= 0.125f; s[nf][1] *= 0.125f;
                s[nf][2] *= 0.125f; s[nf][3] *= 0.125f;
            }
        } else {
            int j0 = jt * 128;
            #pragma unroll
            for (int nf = 0; nf < 16; nf++) {
                int jc = j0 + nf * 8 + 2 * (lane & 3);
                int2 ma = *(const int2*)(m1 + jc);
                int2 mb = *(const int2*)(m2 + jc);
                s[nf][0] = (ma.x == 0) ? -1e30f : s[nf][0] * 0.125f;
                s[nf][1] = (ma.y == 0) ? -1e30f : s[nf][1] * 0.125f;
                s[nf][2] = (mb.x == 0) ? -1e30f : s[nf][2] * 0.125f;
                s[nf][3] = (mb.y == 0) ? -1e30f : s[nf][3] * 0.125f;
            }
        }

        // ---- online softmax ----
        float tmA = -1e30f, tmB = -1e30f;
        #pragma unroll
        for (int nf = 0; nf < 16; nf++) {
            tmA = fmaxf(tmA, fmaxf(s[nf][0], s[nf][1]));
            tmB = fmaxf(tmB, fmaxf(s[nf][2], s[nf][3]));
        }
        #pragma unroll
        for (int off = 1; off <= 2; off <<= 1) {
            tmA = fmaxf(tmA, __shfl_xor_sync(0xffffffffu, tmA, off));
            tmB = fmaxf(tmB, __shfl_xor_sync(0xffffffffu, tmB, off));
        }
        float mnA = fmaxf(mA, tmA), mnB = fmaxf(mB, tmB);
        float aA = __expf(mA - mnA), aB = __expf(mB - mnB);
        mA = mnA; mB = mnB;

        float tsA = 0.f, tsB = 0.f;
        #pragma unroll
        for (int nf = 0; nf < 16; nf++) {
            s[nf][0] = __expf(s[nf][0] - mA);
            s[nf][1] = __expf(s[nf][1] - mA);
            s[nf][2] = __expf(s[nf][2] - mB);
            s[nf][3] = __expf(s[nf][3] - mB);
            tsA += s[nf][0] + s[nf][1];
            tsB += s[nf][2] + s[nf][3];
        }
        #pragma unroll
        for (int off = 1; off <= 2; off <<= 1) {
            tsA += __shfl_xor_sync(0xffffffffu, tsA, off);
            tsB += __shfl_xor_sync(0xffffffffu, tsB, off);
        }
        lA = lA * aA + tsA;
        lB = lB * aB + tsB;
        #pragma unroll
        for (int nf = 0; nf < 8; nf++) {
            o[nf][0] *= aA; o[nf][1] *= aA;
            o[nf][2] *= aB; o[nf][3] *= aB;
        }

        // ---- O += P V ----
        #pragma unroll
        for (int ksp = 0; ksp < 4; ksp++) {
            uint32_t pah0[4], pal0[4], pah1[4], pal1[4];
            cvt2(s[4*ksp+0][0], s[4*ksp+0][1], pah0[0], pal0[0]);
            cvt2(s[4*ksp+0][2], s[4*ksp+0][3], pah0[1], pal0[1]);
            cvt2(s[4*ksp+1][0], s[4*ksp+1][1], pah0[2], pal0[2]);
            cvt2(s[4*ksp+1][2], s[4*ksp+1][3], pah0[3], pal0[3]);
            cvt2(s[4*ksp+2][0], s[4*ksp+2][1], pah1[0], pal1[0]);
            cvt2(s[4*ksp+2][2], s[4*ksp+2][3], pah1[1], pal1[1]);
            cvt2(s[4*ksp+3][0], s[4*ksp+3][1], pah1[2], pal1[2]);
            cvt2(s[4*ksp+3][2], s[4*ksp+3][3], pah1[3], pal1[3]);
            #pragma unroll
            for (int nf = 0; nf < 8; nf++) {
                uint32_t vh[4], vl[4];
                uint32_t va = sV + (ksp * 32 + lane) * 144 + nf * 16;
                LDMX4T(vh, va);
                LDMX4T(vl, va + FST);
                MMA16816(o[nf], pah0, &vh[0]);
                MMA16816(o[nf], pah0, &vl[0]);
                MMA16816(o[nf], pal0, &vh[0]);
                MMA16816(o[nf], pah1, &vh[2]);
                MMA16816(o[nf], pah1, &vl[2]);
                MMA16816(o[nf], pal1, &vh[2]);
            }
        }
        __syncthreads();
    }

    float invA = 1.0f / lA, invB = 1.0f / lB;
    float* outp = g_att + ((size_t)b * TT + rowA) * D_MODEL + h * HD + 2 * (lane & 3);
    #pragma unroll
    for (int nf = 0; nf < 8; nf++) {
        *(float2*)(outp + nf * 8) =
            make_float2(o[nf][0] * invA, o[nf][1] * invA);
        *(float2*)(outp + 8 * D_MODEL + nf * 8) =
            make_float2(o[nf][2] * invB, o[nf][3] * invB);
    }
#undef LOAD_KV
}

// ---------------------------------------------------------------------------
extern "C" void kernel_launch(void* const* d_in, const int* in_sizes, int n_in,
                              void* d_out, int out_size)
{
    const float* query = (const float*)d_in[0];
    const float* key   = (const float*)d_in[1];
    const float* value = (const float*)d_in[2];
    const int*   mask  = (const int*)d_in[3];
    const float* wq = (const float*)d_in[4];
    const float* bq = (const float*)d_in[5];
    const float* wk = (const float*)d_in[6];
    const float* bk = (const float*)d_in[7];
    const float* wv = (const float*)d_in[8];
    const float* bv = (const float*)d_in[9];
    const float* wo = (const float*)d_in[10];
    const float* bo = (const float*)d_in[11];
    float* out = (float*)d_out;

    cudaFuncSetAttribute(tc_gemm_qkv,
                         cudaFuncAttributeMaxDynamicSharedMemorySize, GEMM_SMEM);
    cudaFuncSetAttribute(tc_gemm_o,
                         cudaFuncAttributeMaxDynamicSharedMemorySize, GEMM_SMEM);
    cudaFuncSetAttribute(flash_attn,
                         cudaFuncAttributeMaxDynamicSharedMemorySize, FLASH_SMEM);

    const int ACT4 = MTOT * D_MODEL / 4;     // 1048576
    const int W4   = D_MODEL * D_MODEL / 4;  // 262144

    split_w4<<<dim3(W4 / 256, 4), 256>>>(wq, wk, wv, wo);
    split_a3<<<dim3(ACT4 / 256, 3), 256>>>(query, key, value);
    mask_flags<<<dim3(16, 16, 2), 256>>>(mask);

    tc_gemm_qkv<<<dim3(8, 32, 3), 256, GEMM_SMEM>>>(bq, bk, bv);

    flash_attn<<<dim3(TT / 128, BB * NH), 256, FLASH_SMEM>>>(mask);

    split_att<<<ACT4 / 256, 256>>>();
    tc_gemm_o<<<dim3(8, 32), 256, GEMM_SMEM>>>(bo, out);
}

// round 9
// speedup vs baseline: 3.2527x; 1.0413x over previous
#include <cuda_runtime.h>
#include <cuda_bf16.h>
#include <cstdint>

#define D_MODEL 1024
#define NH 16
#define HD 64
#define BB 2
#define TT 2048
#define MTOT (BB*TT)   // 4096

// bf16 hi/lo split scratch: activations 3 slices (q,k,v; att reuses slice 0)
__device__ __nv_bfloat16 g_ahi[3*MTOT*D_MODEL];
__device__ __nv_bfloat16 g_alo[3*MTOT*D_MODEL];
// weights: 4 slices (wq, wk, wv, wo)
__device__ __nv_bfloat16 g_whi[4*D_MODEL*D_MODEL];
__device__ __nv_bfloat16 g_wlo[4*D_MODEL*D_MODEL];

// Q/K/V in (b,h,t,d) layout, bf16 hi/lo pairs
__device__ __nv_bfloat16 g_Qhi[BB*NH*TT*HD];
__device__ __nv_bfloat16 g_Qlo[BB*NH*TT*HD];
__device__ __nv_bfloat16 g_Khi[BB*NH*TT*HD];
__device__ __nv_bfloat16 g_Klo[BB*NH*TT*HD];
__device__ __nv_bfloat16 g_Vhi[BB*NH*TT*HD];
__device__ __nv_bfloat16 g_Vlo[BB*NH*TT*HD];

// mask block flags: [b][qt][kt] over 128x128 blocks, 1 = fully unmasked
__device__ int g_mflag[BB*16*16];

// ===========================================================================
// helpers
// ===========================================================================
__device__ __forceinline__ uint32_t smem_u32(const void* p) {
    uint32_t a;
    asm("{ .reg .u64 t; cvta.to.shared.u64 t, %1; cvt.u32.u64 %0, t; }"
        : "=r"(a) : "l"(p));
    return a;
}

__device__ __forceinline__ void cvt_split(float4 v, uint2& hi, uint2& lo) {
    __nv_bfloat162 h01 = __floats2bfloat162_rn(v.x, v.y);
    __nv_bfloat162 h23 = __floats2bfloat162_rn(v.z, v.w);
    float r0 = v.x - __bfloat162float(__low2bfloat16(h01));
    float r1 = v.y - __bfloat162float(__high2bfloat16(h01));
    float r2 = v.z - __bfloat162float(__low2bfloat16(h23));
    float r3 = v.w - __bfloat162float(__high2bfloat16(h23));
    __nv_bfloat162 l01 = __floats2bfloat162_rn(r0, r1);
    __nv_bfloat162 l23 = __floats2bfloat162_rn(r2, r3);
    hi.x = *(uint32_t*)&h01; hi.y = *(uint32_t*)&h23;
    lo.x = *(uint32_t*)&l01; lo.y = *(uint32_t*)&l23;
}

__device__ __forceinline__ void cvt2(float a, float b, uint32_t& hi, uint32_t& lo) {
    __nv_bfloat162 h = __floats2bfloat162_rn(a, b);
    float ra = a - __bfloat162float(__low2bfloat16(h));
    float rb = b - __bfloat162float(__high2bfloat16(h));
    __nv_bfloat162 l = __floats2bfloat162_rn(ra, rb);
    hi = *(uint32_t*)&h; lo = *(uint32_t*)&l;
}

#define LDMX4(r, addr) \
    asm volatile("ldmatrix.sync.aligned.m8n8.x4.shared.b16 {%0,%1,%2,%3}, [%4];" \
        : "=r"((r)[0]), "=r"((r)[1]), "=r"((r)[2]), "=r"((r)[3]) : "r"(addr))

#define LDMX4T(r, addr) \
    asm volatile("ldmatrix.sync.aligned.m8n8.x4.trans.shared.b16 {%0,%1,%2,%3}, [%4];" \
        : "=r"((r)[0]), "=r"((r)[1]), "=r"((r)[2]), "=r"((r)[3]) : "r"(addr))

#define MMA16816(c, a, b) \
    asm volatile("mma.sync.aligned.m16n8k16.row.col.f32.bf16.bf16.f32 " \
        "{%0,%1,%2,%3}, {%4,%5,%6,%7}, {%8,%9}, {%0,%1,%2,%3};" \
        : "+f"((c)[0]), "+f"((c)[1]), "+f"((c)[2]), "+f"((c)[3]) \
        : "r"((a)[0]), "r"((a)[1]), "r"((a)[2]), "r"((a)[3]), \
          "r"((b)[0]), "r"((b)[1]))

#define CP_ASYNC16(dst, src) \
    asm volatile("cp.async.cg.shared.global [%0], [%1], 16;" \
        :: "r"(dst), "l"(src))
#define CP_COMMIT() asm volatile("cp.async.commit_group;" ::: "memory")
#define CP_WAIT1()  asm volatile("cp.async.wait_group 1;" ::: "memory")
#define CP_WAIT0()  asm volatile("cp.async.wait_group 0;" ::: "memory")

// ===========================================================================
// Split kernels
// ===========================================================================
__global__ void __launch_bounds__(256) split_a3(
    const float* __restrict__ q, const float* __restrict__ k,
    const float* __restrict__ v)
{
    int z = blockIdx.y;
    int i = blockIdx.x * 256 + threadIdx.x;
    const float* src = (z == 0) ? q : (z == 1) ? k : v;
    float4 val = ((const float4*)src)[i];
    uint2 hi, lo;
    cvt_split(val, hi, lo);
    size_t off = (size_t)z * (MTOT * D_MODEL / 4) + i;
    ((uint2*)g_ahi)[off] = hi;
    ((uint2*)g_alo)[off] = lo;
}

__global__ void __launch_bounds__(256) split_w4(
    const float* __restrict__ wq, const float* __restrict__ wk,
    const float* __restrict__ wv, const float* __restrict__ wo)
{
    int z = blockIdx.y;
    int i = blockIdx.x * 256 + threadIdx.x;
    const float* src = (z == 0) ? wq : (z == 1) ? wk : (z == 2) ? wv : wo;
    float4 v = ((const float4*)src)[i];
    uint2 hi, lo;
    cvt_split(v, hi, lo);
    size_t off = (size_t)z * (D_MODEL * D_MODEL / 4) + i;
    ((uint2*)g_whi)[off] = hi;
    ((uint2*)g_wlo)[off] = lo;
}

// ===========================================================================
// Mask block flags (128x128 blocks)
// ===========================================================================
__global__ void __launch_bounds__(256) mask_flags(const int* __restrict__ mask)
{
    int qt = blockIdx.x, kt = blockIdx.y, b = blockIdx.z;
    int t = threadIdx.x;
    const int* mp = mask + ((size_t)b * TT + qt * 128) * TT + kt * 128;
    int row = t >> 1, ch = (t & 1) * 64;
    bool ok = true;
    #pragma unroll
    for (int i = 0; i < 16; i++) {
        int4 v = *(const int4*)(mp + (size_t)row * TT + ch + i * 4);
        ok = ok && v.x && v.y && v.z && v.w;
    }
    int all = __syncthreads_and((int)ok);
    if (t == 0) g_mflag[(b * 16 + qt) * 16 + kt] = all;
}

// ===========================================================================
// HMMA GEMM with bf16 split. B-operand loads paired via LDMX4.
// ===========================================================================
#define LDSB 80
#define TILE_B (128*LDSB)
#define STAGE_B (4*TILE_B)
#define GEMM_SMEM (2*STAGE_B)    // 81920 B

#define GEMM_LOAD(kc, stg) do {                                               \
    uint32_t sb0 = smb + (stg) * STAGE_B + tile * TILE_B;                     \
    _Pragma("unroll")                                                         \
    for (int j = 0; j < 8; j++) {                                             \
        int rem = ltid + j * 64;                                              \
        int row = rem >> 2, cc = rem & 3;                                     \
        const __nv_bfloat16* gp =                                             \
            lsrc + (size_t)(grow0 + row) * D_MODEL + (kc) * 32 + cc * 8;      \
        uint32_t dst = sb0 + row * LDSB + cc * 16;                            \
        CP_ASYNC16(dst, gp);                                                  \
    }                                                                         \
    CP_COMMIT();                                                              \
} while (0)

// Shared GEMM mainloop body (acc in caller scope)
#define GEMM_MAIN()                                                           \
    uint32_t arow = warp_m * 64 + (lane & 7) + ((lane >> 3) & 1) * 8;         \
    uint32_t acol = ((lane >> 4) & 1) * 16;                                   \
    uint32_t brow2 = warp_n * 32 + ((lane >> 4) & 1) * 8 + (lane & 7);        \
    uint32_t bcol2 = ((lane >> 3) & 1) * 16;                                  \
    GEMM_LOAD(0, 0);                                                          \
    for (int kc = 0; kc < D_MODEL / 32; kc++) {                               \
        if (kc + 1 < D_MODEL / 32) {                                          \
            GEMM_LOAD(kc + 1, (kc + 1) & 1);                                  \
            CP_WAIT1();                                                       \
        } else {                                                              \
            CP_WAIT0();                                                       \
        }                                                                     \
        __syncthreads();                                                      \
        uint32_t sb = smb + (kc & 1) * STAGE_B;                               \
        uint32_t abase = sb + arow * LDSB + acol;                             \
        uint32_t bbase = sb + 2 * TILE_B + brow2 * LDSB + bcol2;              \
        _Pragma("unroll")                                                     \
        for (int s = 0; s < 2; s++) {                                         \
            uint32_t bh4[2][4], bl4[2][4];                                    \
            _Pragma("unroll")                                                 \
            for (int jp = 0; jp < 2; jp++) {                                  \
                uint32_t ad = bbase + jp * 16 * LDSB + s * 32;                \
                LDMX4(bh4[jp], ad);                                           \
                LDMX4(bl4[jp], ad + TILE_B);                                  \
            }                                                                 \
            _Pragma("unroll")                                                 \
            for (int im = 0; im < 4; im++) {                                  \
                uint32_t ah[4], al[4];                                        \
                uint32_t ad = abase + im * 16 * LDSB + s * 32;                \
                LDMX4(ah, ad);                                                \
                LDMX4(al, ad + TILE_B);                                       \
                _Pragma("unroll")                                             \
                for (int jp = 0; jp < 2; jp++) {                              \
                    MMA16816(acc[im][2*jp],   ah, &bh4[jp][0]);               \
                    MMA16816(acc[im][2*jp],   ah, &bl4[jp][0]);               \
                    MMA16816(acc[im][2*jp],   al, &bh4[jp][0]);               \
                    MMA16816(acc[im][2*jp+1], ah, &bh4[jp][2]);               \
                    MMA16816(acc[im][2*jp+1], ah, &bl4[jp][2]);               \
                    MMA16816(acc[im][2*jp+1], al, &bh4[jp][2]);               \
                }                                                             \
            }                                                                 \
        }                                                                     \
        __syncthreads();                                                      \
    }

// QKV fused: grid (8, 32, 3)
__global__ void __launch_bounds__(256, 2) tc_gemm_qkv(
    const float* __restrict__ bq, const float* __restrict__ bk,
    const float* __restrict__ bv)
{
    extern __shared__ char smc[];
    uint32_t smb = smem_u32(smc);
    int tid = threadIdx.x;
    int lane = tid & 31;
    int wid = tid >> 5;
    int warp_m = wid & 1;
    int warp_n = wid >> 1;
    int m0 = blockIdx.y * 128;
    int n0 = blockIdx.x * 128;
    int z = blockIdx.z;
    const float* bias = (z == 0) ? bq : (z == 1) ? bk : bv;

    int tile = tid >> 6;
    int ltid = tid & 63;
    const __nv_bfloat16* lsrc =
        (tile == 0) ? g_ahi + (size_t)z * MTOT * D_MODEL
      : (tile == 1) ? g_alo + (size_t)z * MTOT * D_MODEL
      : (tile == 2) ? g_whi + (size_t)z * D_MODEL * D_MODEL
                    : g_wlo + (size_t)z * D_MODEL * D_MODEL;
    int grow0 = (tile < 2) ? m0 : n0;

    float acc[4][4][4];
    #pragma unroll
    for (int i = 0; i < 4; i++)
        #pragma unroll
        for (int j = 0; j < 4; j++)
            #pragma unroll
            for (int r = 0; r < 4; r++)
                acc[i][j][r] = 0.f;

    GEMM_MAIN();

    __nv_bfloat16* dhi = (z == 0) ? g_Qhi : (z == 1) ? g_Khi : g_Vhi;
    __nv_bfloat16* dlo = (z == 0) ? g_Qlo : (z == 1) ? g_Klo : g_Vlo;
    #pragma unroll
    for (int im = 0; im < 4; im++) {
        #pragma unroll
        for (int jn = 0; jn < 4; jn++) {
            int m = m0 + warp_m * 64 + im * 16 + (lane >> 2);
            int n = n0 + warp_n * 32 + jn * 8 + (lane & 3) * 2;
            float2 bv2 = *(const float2*)&bias[n];
            float2 v01 = make_float2(acc[im][jn][0] + bv2.x, acc[im][jn][1] + bv2.y);
            float2 v23 = make_float2(acc[im][jn][2] + bv2.x, acc[im][jn][3] + bv2.y);
            int h = n >> 6, d = n & 63;
            int b = m >> 11, t = m & 2047;
            size_t off = (((size_t)b * NH + h) * TT + t) * HD + d;
            uint32_t hi0, lo0, hi1, lo1;
            cvt2(v01.x, v01.y, hi0, lo0);
            cvt2(v23.x, v23.y, hi1, lo1);
            *(uint32_t*)(dhi + off) = hi0;
            *(uint32_t*)(dlo + off) = lo0;
            *(uint32_t*)(dhi + off + 8 * HD) = hi1;
            *(uint32_t*)(dlo + off + 8 * HD) = lo1;
        }
    }
}

// Output projection: A slice 0, W slice 3, flat fp32 out
__global__ void __launch_bounds__(256, 2) tc_gemm_o(
    const float* __restrict__ bias, float* __restrict__ Cflat)
{
    extern __shared__ char smc[];
    uint32_t smb = smem_u32(smc);
    int tid = threadIdx.x;
    int lane = tid & 31;
    int wid = tid >> 5;
    int warp_m = wid & 1;
    int warp_n = wid >> 1;
    int m0 = blockIdx.y * 128;
    int n0 = blockIdx.x * 128;

    int tile = tid >> 6;
    int ltid = tid & 63;
    const __nv_bfloat16* lsrc =
        (tile == 0) ? g_ahi
      : (tile == 1) ? g_alo
      : (tile == 2) ? g_whi + (size_t)3 * D_MODEL * D_MODEL
                    : g_wlo + (size_t)3 * D_MODEL * D_MODEL;
    int grow0 = (tile < 2) ? m0 : n0;

    float acc[4][4][4];
    #pragma unroll
    for (int i = 0; i < 4; i++)
        #pragma unroll
        for (int j = 0; j < 4; j++)
            #pragma unroll
            for (int r = 0; r < 4; r++)
                acc[i][j][r] = 0.f;

    GEMM_MAIN();

    #pragma unroll
    for (int im = 0; im < 4; im++) {
        #pragma unroll
        for (int jn = 0; jn < 4; jn++) {
            int m = m0 + warp_m * 64 + im * 16 + (lane >> 2);
            int n = n0 + warp_n * 32 + jn * 8 + (lane & 3) * 2;
            float2 bv2 = *(const float2*)&bias[n];
            *(float2*)(Cflat + (size_t)m * D_MODEL + n) =
                make_float2(acc[im][jn][0] + bv2.x, acc[im][jn][1] + bv2.y);
            *(float2*)(Cflat + (size_t)(m + 8) * D_MODEL + n) =
                make_float2(acc[im][jn][2] + bv2.x, acc[im][jn][3] + bv2.y);
        }
    }
}

// ===========================================================================
// HMMA flash attention, 64-key tiles, 2 CTAs/SM.
// CTA: 128 queries of one (b,h); 8 warps, each owns 16 rows.
// Epilogue writes bf16 hi/lo straight into activation slice 0 for O-proj.
// ===========================================================================
#define KVR 64                     // keys per stage
#define KVT (KVR*144)              // 9216 B per tensor tile
#define KVSTG (4*KVT)              // 36864 (Khi,Klo,Vhi,Vlo)
#define QTB 18432                  // Q tile (128 x 144)
#define F_QHI (2*KVSTG)            // 73728
#define F_QLO (F_QHI + QTB)
#define FLASH_SMEM (F_QLO + QTB)   // 110592 B

__global__ void __launch_bounds__(256, 2) flash_attn(const int* __restrict__ mask)
{
    extern __shared__ char smc[];
    uint32_t smb = smem_u32(smc);
    int tid = threadIdx.x;
    int lane = tid & 31;
    int wid = tid >> 5;

    int bh = blockIdx.y;
    int b = bh >> 4;
    int h = bh & 15;
    int q0 = blockIdx.x * 128;

    // stage Q (hi+lo) once
    #pragma unroll
    for (int i = 0; i < 8; i++) {
        int c = tid + i * 256;
        int tens = c >> 10, c2 = c & 1023;
        int row = c2 >> 3, ch = c2 & 7;
        const __nv_bfloat16* src = (tens ? g_Qlo : g_Qhi)
            + ((size_t)bh * TT + q0 + row) * HD + ch * 8;
        CP_ASYNC16(smb + F_QHI + tens * QTB + row * 144 + ch * 16, src);
    }
    CP_COMMIT();

    int ltile = tid >> 6;
    int ltid = tid & 63;
    const __nv_bfloat16* lsrc0 =
        ((ltile == 0) ? g_Khi : (ltile == 1) ? g_Klo
                      : (ltile == 2) ? g_Vhi : g_Vlo) + (size_t)bh * TT * HD;

#define LOAD_KV(j0, stg) do {                                                 \
    const __nv_bfloat16* src = lsrc0 + (size_t)(j0) * HD;                     \
    uint32_t dstb = smb + (stg) * KVSTG + ltile * KVT;                        \
    _Pragma("unroll")                                                         \
    for (int i = 0; i < 8; i++) {                                             \
        int c = ltid + i * 64;                                                \
        int row = c >> 3, ch = c & 7;                                         \
        CP_ASYNC16(dstb + row * 144 + ch * 16, src + row * HD + ch * 8);      \
    }                                                                         \
    CP_COMMIT();                                                              \
} while (0)

    LOAD_KV(0, 0);

    int rowA = q0 + wid * 16 + (lane >> 2);
    const int* m1 = mask + (size_t)b * TT * TT + (size_t)rowA * TT;
    const int* m2 = m1 + 8 * (size_t)TT;
    const int* fl = g_mflag + (b * 16 + blockIdx.x) * 16;

    float o[8][4];
    #pragma unroll
    for (int i = 0; i < 8; i++)
        #pragma unroll
        for (int r = 0; r < 4; r++) o[i][r] = 0.f;
    float mA = -1e30f, mB = -1e30f, lA = 0.f, lB = 0.f;

    uint32_t qbase = smb + F_QHI
        + (wid * 16 + (lane & 7) + ((lane >> 3) & 1) * 8) * 144
        + ((lane >> 4) & 1) * 16;

    for (int jt = 0; jt < TT / KVR; jt++) {
        if (jt + 1 < TT / KVR) {
            LOAD_KV((jt + 1) * KVR, (jt + 1) & 1);
            CP_WAIT1();
        } else {
            CP_WAIT0();
        }
        __syncthreads();

        uint32_t sK = smb + (jt & 1) * KVSTG;
        uint32_t sV = sK + 2 * KVT;

        // ---- S = Q K^T  (16x64 per warp) ----
        float s[8][4];
        #pragma unroll
        for (int i = 0; i < 8; i++)
            #pragma unroll
            for (int r = 0; r < 4; r++) s[i][r] = 0.f;

        #pragma unroll
        for (int ksp = 0; ksp < 2; ksp++) {
            uint32_t ah0[4], ah1[4], al0[4], al1[4];
            uint32_t qa = qbase + ksp * 64;
            LDMX4(ah0, qa);
            LDMX4(ah1, qa + 32);
            LDMX4(al0, qa + QTB);
            LDMX4(al1, qa + QTB + 32);
            #pragma unroll
            for (int nf = 0; nf < 8; nf++) {
                uint32_t kb[4], kl[4];
                uint32_t ka = sK + (nf * 8 + (lane & 7)) * 144
                            + ksp * 64 + (lane >> 3) * 16;
                LDMX4(kb, ka);
                LDMX4(kl, ka + KVT);
                MMA16816(s[nf], ah0, &kb[0]);
                MMA16816(s[nf], ah0, &kl[0]);
                MMA16816(s[nf], al0, &kb[0]);
                MMA16816(s[nf], ah1, &kb[2]);
                MMA16816(s[nf], ah1, &kl[2]);
                MMA16816(s[nf], al1, &kb[2]);
            }
        }

        // ---- scale + mask (block-flag fast path) ----
        if (fl[jt >> 1]) {
            #pragma unroll
            for (int nf = 0; nf < 8; nf++) {
                s[nf][0] *= 0.125f; s[nf][1] *= 0.125f;
                s[nf][2] *= 0.125f; s[nf][3] *= 0.125f;
            }
        } else {
            int j0 = jt * KVR;
            #pragma unroll
            for (int nf = 0; nf < 8; nf++) {
                int jc = j0 + nf * 8 + 2 * (lane & 3);
                int2 ma = *(const int2*)(m1 + jc);
                int2 mb = *(const int2*)(m2 + jc);
                s[nf][0] = (ma.x == 0) ? -1e30f : s[nf][0] * 0.125f;
                s[nf][1] = (ma.y == 0) ? -1e30f : s[nf][1] * 0.125f;
                s[nf][2] = (mb.x == 0) ? -1e30f : s[nf][2] * 0.125f;
                s[nf][3] = (mb.y == 0) ? -1e30f : s[nf][3] * 0.125f;
            }
        }

        // ---- online softmax ----
        float tmA = -1e30f, tmB = -1e30f;
        #pragma unroll
        for (int nf = 0; nf < 8; nf++) {
            tmA = fmaxf(tmA, fmaxf(s[nf][0], s[nf][1]));
            tmB = fmaxf(tmB, fmaxf(s[nf][2], s[nf][3]));
        }
        #pragma unroll
        for (int off = 1; off <= 2; off <<= 1) {
            tmA = fmaxf(tmA, __shfl_xor_sync(0xffffffffu, tmA, off));
            tmB = fmaxf(tmB, __shfl_xor_sync(0xffffffffu, tmB, off));
        }
        float mnA = fmaxf(mA, tmA), mnB = fmaxf(mB, tmB);
        float aA = __expf(mA - mnA), aB = __expf(mB - mnB);
        mA = mnA; mB = mnB;

        float tsA = 0.f, tsB = 0.f;
        #pragma unroll
        for (int nf = 0; nf < 8; nf++) {
            s[nf][0] = __expf(s[nf][0] - mA);
            s[nf][1] = __expf(s[nf][1] - mA);
            s[nf][2] = __expf(s[nf][2] - mB);
            s[nf][3] = __expf(s[nf][3] - mB);
            tsA += s[nf][0] + s[nf][1];
            tsB += s[nf][2] + s[nf][3];
        }
        #pragma unroll
        for (int off = 1; off <= 2; off <<= 1) {
            tsA += __shfl_xor_sync(0xffffffffu, tsA, off);
            tsB += __shfl_xor_sync(0xffffffffu, tsB, off);
        }
        lA = lA * aA + tsA;
        lB = lB * aB + tsB;
        #pragma unroll
        for (int nf = 0; nf < 8; nf++) {
            o[nf][0] *= aA; o[nf][1] *= aA;
            o[nf][2] *= aB; o[nf][3] *= aB;
        }

        // ---- O += P V ----
        #pragma unroll
        for (int ksp = 0; ksp < 2; ksp++) {
            uint32_t pah0[4], pal0[4], pah1[4], pal1[4];
            cvt2(s[4*ksp+0][0], s[4*ksp+0][1], pah0[0], pal0[0]);
            cvt2(s[4*ksp+0][2], s[4*ksp+0][3], pah0[1], pal0[1]);
            cvt2(s[4*ksp+1][0], s[4*ksp+1][1], pah0[2], pal0[2]);
            cvt2(s[4*ksp+1][2], s[4*ksp+1][3], pah0[3], pal0[3]);
            cvt2(s[4*ksp+2][0], s[4*ksp+2][1], pah1[0], pal1[0]);
            cvt2(s[4*ksp+2][2], s[4*ksp+2][3], pah1[1], pal1[1]);
            cvt2(s[4*ksp+3][0], s[4*ksp+3][1], pah1[2], pal1[2]);
            cvt2(s[4*ksp+3][2], s[4*ksp+3][3], pah1[3], pal1[3]);
            #pragma unroll
            for (int nf = 0; nf < 8; nf++) {
                uint32_t vh[4], vl[4];
                uint32_t va = sV + (ksp * 32 + lane) * 144 + nf * 16;
                LDMX4T(vh, va);
                LDMX4T(vl, va + KVT);
                MMA16816(o[nf], pah0, &vh[0]);
                MMA16816(o[nf], pah0, &vl[0]);
                MMA16816(o[nf], pal0, &vh[0]);
                MMA16816(o[nf], pah1, &vh[2]);
                MMA16816(o[nf], pah1, &vl[2]);
                MMA16816(o[nf], pal1, &vh[2]);
            }
        }
        __syncthreads();
    }

    // ---- epilogue: normalize, split to bf16 hi/lo in activation slice 0 ----
    float invA = 1.0f / lA, invB = 1.0f / lB;
    size_t base = ((size_t)b * TT + rowA) * D_MODEL + h * HD + 2 * (lane & 3);
    #pragma unroll
    for (int nf = 0; nf < 8; nf++) {
        uint32_t hi, lo;
        cvt2(o[nf][0] * invA, o[nf][1] * invA, hi, lo);
        *(uint32_t*)(g_ahi + base + nf * 8) = hi;
        *(uint32_t*)(g_alo + base + nf * 8) = lo;
        cvt2(o[nf][2] * invB, o[nf][3] * invB, hi, lo);
        *(uint32_t*)(g_ahi + base + 8 * D_MODEL + nf * 8) = hi;
        *(uint32_t*)(g_alo + base + 8 * D_MODEL + nf * 8) = lo;
    }
#undef LOAD_KV
}

// ---------------------------------------------------------------------------
extern "C" void kernel_launch(void* const* d_in, const int* in_sizes, int n_in,
                              void* d_out, int out_size)
{
    const float* query = (const float*)d_in[0];
    const float* key   = (const float*)d_in[1];
    const float* value = (const float*)d_in[2];
    const int*   mask  = (const int*)d_in[3];
    const float* wq = (const float*)d_in[4];
    const float* bq = (const float*)d_in[5];
    const float* wk = (const float*)d_in[6];
    const float* bk = (const float*)d_in[7];
    const float* wv = (const float*)d_in[8];
    const float* bv = (const float*)d_in[9];
    const float* wo = (const float*)d_in[10];
    const float* bo = (const float*)d_in[11];
    float* out = (float*)d_out;

    cudaFuncSetAttribute(tc_gemm_qkv,
                         cudaFuncAttributeMaxDynamicSharedMemorySize, GEMM_SMEM);
    cudaFuncSetAttribute(tc_gemm_o,
                         cudaFuncAttributeMaxDynamicSharedMemorySize, GEMM_SMEM);
    cudaFuncSetAttribute(flash_attn,
                         cudaFuncAttributeMaxDynamicSharedMemorySize, FLASH_SMEM);

    const int ACT4 = MTOT * D_MODEL / 4;     // 1048576
    const int W4   = D_MODEL * D_MODEL / 4;  // 262144

    split_w4<<<dim3(W4 / 256, 4), 256>>>(wq, wk, wv, wo);
    split_a3<<<dim3(ACT4 / 256, 3), 256>>>(query, key, value);
    mask_flags<<<dim3(16, 16, 2), 256>>>(mask);

    tc_gemm_qkv<<<dim3(8, 32, 3), 256, GEMM_SMEM>>>(bq, bk, bv);

    flash_attn<<<dim3(TT / 128, BB * NH), 256, FLASH_SMEM>>>(mask);

    tc_gemm_o<<<dim3(8, 32), 256, GEMM_SMEM>>>(bo, out);
}